// round 12
// baseline (speedup 1.0000x reference)
#include <cuda_runtime.h>
#include <cuda_fp16.h>
#include <cuda_bf16.h>
#include <math.h>
#include <stdint.h>

#define BATCH 2
#define KLEN  512
#define LSEQ  1024
#define EMB   1024
#define NHEAD 16
#define DHEAD 64
#define NLAYER 12
#define FFDIM 4096
#define DIN   64
#define LN_EPS 1e-5f
#define MROWS (BATCH * LSEQ)   // 2048
#define NBH   (BATCH * NHEAD)  // 32

// ---------------------------------------------------------------------------
// Scratch (device globals; zero-initialized; allocation forbidden)
// ---------------------------------------------------------------------------
__device__ float g_x [MROWS * EMB];
__device__ __half g_h[MROWS * EMB];       // ln out (fp16)
__device__ __half g_a[MROWS * EMB];       // attn out (fp16)
__device__ __half g_f[MROWS * FFDIM];     // mlp hidden (fp16)
// attention operands (bf16 hi/lo)
__device__ __nv_bfloat16 g_qh[NBH * LSEQ * DHEAD];
__device__ __nv_bfloat16 g_ql[NBH * LSEQ * DHEAD];
__device__ __nv_bfloat16 g_kh[NBH * LSEQ * DHEAD];
__device__ __nv_bfloat16 g_kl[NBH * LSEQ * DHEAD];
__device__ __nv_bfloat16 g_vth[NBH * DHEAD * LSEQ];   // V transposed [bh][d][l]
__device__ __nv_bfloat16 g_vtl[NBH * DHEAD * LSEQ];
// transposed + split weights: [layer][N][K], fp16 hi + lo
__device__ __half g_wqh[NLAYER * 3 * EMB * EMB];
__device__ __half g_wql[NLAYER * 3 * EMB * EMB];
__device__ __half g_wph[NLAYER * EMB * EMB];
__device__ __half g_wpl[NLAYER * EMB * EMB];
__device__ __half g_w1h[NLAYER * FFDIM * EMB];
__device__ __half g_w1l[NLAYER * FFDIM * EMB];
__device__ __half g_w2h[NLAYER * EMB * FFDIM];
__device__ __half g_w2l[NLAYER * EMB * FFDIM];

// ---------------------------------------------------------------------------
// Helpers
// ---------------------------------------------------------------------------
__device__ __forceinline__ uint32_t smem_u32(const void* p) {
    uint32_t a;
    asm("{ .reg .u64 t; cvta.to.shared.u64 t, %1; cvt.u32.u64 %0, t; }" : "=r"(a) : "l"(p));
    return a;
}
__device__ __forceinline__ void cp_async16(uint32_t s, const void* g) {
    asm volatile("cp.async.cg.shared.global [%0], [%1], 16;" :: "r"(s), "l"(g));
}
#define CP_COMMIT() asm volatile("cp.async.commit_group;" ::: "memory")
#define CP_WAIT(n)  asm volatile("cp.async.wait_group %0;" :: "n"(n) : "memory")

__device__ __forceinline__ void ldsm4(uint32_t a, uint32_t& r0, uint32_t& r1,
                                      uint32_t& r2, uint32_t& r3) {
    asm volatile("ldmatrix.sync.aligned.m8n8.x4.shared.b16 {%0,%1,%2,%3}, [%4];"
                 : "=r"(r0), "=r"(r1), "=r"(r2), "=r"(r3) : "r"(a));
}
__device__ __forceinline__ void mma_f16(float* d, const uint32_t* a, const uint32_t* b) {
    asm volatile(
        "mma.sync.aligned.m16n8k16.row.col.f32.f16.f16.f32 "
        "{%0,%1,%2,%3}, {%4,%5,%6,%7}, {%8,%9}, {%0,%1,%2,%3};"
        : "+f"(d[0]), "+f"(d[1]), "+f"(d[2]), "+f"(d[3])
        : "r"(a[0]), "r"(a[1]), "r"(a[2]), "r"(a[3]), "r"(b[0]), "r"(b[1]));
}
__device__ __forceinline__ void mma_bf16(float* d, const uint32_t* a, const uint32_t* b) {
    asm volatile(
        "mma.sync.aligned.m16n8k16.row.col.f32.bf16.bf16.f32 "
        "{%0,%1,%2,%3}, {%4,%5,%6,%7}, {%8,%9}, {%0,%1,%2,%3};"
        : "+f"(d[0]), "+f"(d[1]), "+f"(d[2]), "+f"(d[3])
        : "r"(a[0]), "r"(a[1]), "r"(a[2]), "r"(a[3]), "r"(b[0]), "r"(b[1]));
}
__device__ __forceinline__ void split_f16(float v, __half& hi, __half& lo) {
    hi = __float2half_rn(v);
    lo = __float2half_rn(v - __half2float(hi));
}
__device__ __forceinline__ void split_bf(float v, __nv_bfloat16& hi, __nv_bfloat16& lo) {
    hi = __float2bfloat16(v);
    lo = __float2bfloat16(v - __bfloat162float(hi));
}
__device__ __forceinline__ void split_pack(float v0, float v1, uint32_t& ph, uint32_t& pl) {
    asm("cvt.rn.bf16x2.f32 %0, %1, %2;" : "=r"(ph) : "f"(v1), "f"(v0));
    float h0 = __uint_as_float(ph << 16);
    float h1 = __uint_as_float(ph & 0xFFFF0000u);
    float r0 = v0 - h0, r1 = v1 - h1;
    asm("cvt.rn.bf16x2.f32 %0, %1, %2;" : "=r"(pl) : "f"(r1), "f"(r0));
}

// ---------------------------------------------------------------------------
// Epilogue (shared)
// EPI: 0 = write qkv splits   1 = residual + fp32 out   2 = GELU + fp16 out
// ---------------------------------------------------------------------------
template <int EPI>
__device__ __forceinline__ void gemm_epilogue_elem(
    int row, int col, float v0, float v1, int N,
    const float* __restrict__ Rres, float* __restrict__ C, __half* __restrict__ Ch)
{
    if (EPI == 0) {
        const int b = row >> 10, l = row & 1023;
        const int part = col >> 10;
        const int h = (col & 1023) >> 6, d = col & 63;
        const int bh = b * NHEAD + h;
        __nv_bfloat16 h0, l0, h1, l1;
        split_bf(v0, h0, l0); split_bf(v1, h1, l1);
        if (part == 2) {
            const size_t o = ((size_t)bh * DHEAD + d) * LSEQ + l;
            g_vth[o] = h0; g_vtl[o] = l0;
            g_vth[o + LSEQ] = h1; g_vtl[o + LSEQ] = l1;
        } else {
            const size_t o = ((size_t)bh * LSEQ + l) * DHEAD + d;
            __nv_bfloat162 hv; hv.x = h0; hv.y = h1;
            __nv_bfloat162 lv; lv.x = l0; lv.y = l1;
            if (part == 0) {
                *(__nv_bfloat162*)(g_qh + o) = hv;
                *(__nv_bfloat162*)(g_ql + o) = lv;
            } else {
                *(__nv_bfloat162*)(g_kh + o) = hv;
                *(__nv_bfloat162*)(g_kl + o) = lv;
            }
        }
    } else {
        const size_t o = (size_t)row * N + col;
        if (EPI == 1) {
            v0 += Rres[o]; v1 += Rres[o + 1];
            float2 fv = {v0, v1}; *(float2*)(C + o) = fv;
        } else {
            v0 = 0.5f * v0 * (1.0f + erff(v0 * 0.70710678118654752f));
            v1 = 0.5f * v1 * (1.0f + erff(v1 * 0.70710678118654752f));
            __half2 hv; hv.x = __float2half_rn(v0); hv.y = __float2half_rn(v1);
            *(__half2*)(Ch + o) = hv;
        }
    }
}

// ---------------------------------------------------------------------------
// Variant A: 128x128 tile, 512 threads, 16 warps 4x4, warp 32x32, 4-stage.
// Used for SMALL grids (proj, mlp2: 128 CTAs).
// ---------------------------------------------------------------------------
#define RSTRIDE 80
#define MAT_BYTES (128 * RSTRIDE)
#define STG_A (3 * MAT_BYTES)
#define NSTG_A 4
#define SMEM_A (NSTG_A * STG_A)            // 122880

template <int EPI>
__global__ void __launch_bounds__(512, 1) gemm_mma512(
    const __half* __restrict__ A,
    const __half* __restrict__ Bh, const __half* __restrict__ Bl,
    const float* __restrict__ bias, const float* __restrict__ Rres,
    float* __restrict__ C, __half* __restrict__ Ch,
    int M, int N, int K)
{
    extern __shared__ char smem[];
    const uint32_t sbase = smem_u32(smem);
    const int tid = threadIdx.x, wid = tid >> 5, lane = tid & 31;
    const int m0 = blockIdx.y * 128, n0 = blockIdx.x * 128;
    const int wm = wid & 3, wn = wid >> 2;
    const int g = lane >> 2, q = lane & 3;
    const int lrow = tid >> 2, lch = tid & 3;
    const uint32_t soff = (uint32_t)(lrow * RSTRIDE + lch * 16);
    const uint32_t aoff = (uint32_t)((wm * 32 + (lane & 15)) * RSTRIDE + (lane >> 4) * 16);
    const uint32_t boff = (uint32_t)((wn * 32 + (lane >> 4) * 8 + (lane & 7)) * RSTRIDE
                                     + ((lane >> 3) & 1) * 16);

    float acc[2][4][4];
#pragma unroll
    for (int i = 0; i < 2; ++i)
#pragma unroll
        for (int j = 0; j < 4; ++j)
#pragma unroll
            for (int r = 0; r < 4; ++r) acc[i][j][r] = 0.f;

    const int CH = K >> 5;
    auto load_stage = [&](int c) {
        const int k0 = c << 5;
        const uint32_t sb = sbase + (c & (NSTG_A - 1)) * STG_A + soff;
        const size_t ga = (size_t)(m0 + lrow) * K + k0 + lch * 8;
        const size_t gb = (size_t)(n0 + lrow) * K + k0 + lch * 8;
        cp_async16(sb,                 A  + ga);
        cp_async16(sb + MAT_BYTES,     Bh + gb);
        cp_async16(sb + 2 * MAT_BYTES, Bl + gb);
    };
    load_stage(0); CP_COMMIT();
    load_stage(1); CP_COMMIT();
    load_stage(2); CP_COMMIT();

    for (int c = 0; c < CH; ++c) {
        CP_WAIT(2);
        __syncthreads();
        const uint32_t sA = sbase + (c & (NSTG_A - 1)) * STG_A;
        const uint32_t sB = sA + MAT_BYTES;
#pragma unroll
        for (int ks = 0; ks < 2; ++ks) {
            uint32_t Af[2][4], Bhf[4][2], Blf[4][2];
#pragma unroll
            for (int mt = 0; mt < 2; ++mt) {
                const uint32_t aa = sA + aoff + mt * 16 * RSTRIDE + ks * 32;
                ldsm4(aa, Af[mt][0], Af[mt][1], Af[mt][2], Af[mt][3]);
            }
#pragma unroll
            for (int p = 0; p < 2; ++p) {
                const uint32_t ba = sB + boff + p * 16 * RSTRIDE + ks * 32;
                ldsm4(ba,             Bhf[2*p][0], Bhf[2*p][1], Bhf[2*p+1][0], Bhf[2*p+1][1]);
                ldsm4(ba + MAT_BYTES, Blf[2*p][0], Blf[2*p][1], Blf[2*p+1][0], Blf[2*p+1][1]);
            }
#pragma unroll
            for (int mt = 0; mt < 2; ++mt)
#pragma unroll
                for (int nt = 0; nt < 4; ++nt)
                    mma_f16(acc[mt][nt], Af[mt], Bhf[nt]);
#pragma unroll
            for (int mt = 0; mt < 2; ++mt)
#pragma unroll
                for (int nt = 0; nt < 4; ++nt)
                    mma_f16(acc[mt][nt], Af[mt], Blf[nt]);
        }
        if (c + 3 < CH) load_stage(c + 3);
        CP_COMMIT();
    }

#pragma unroll
    for (int nt = 0; nt < 4; ++nt) {
        const int col = n0 + wn * 32 + nt * 8 + q * 2;
        const float bia0 = bias[col], bia1 = bias[col + 1];
#pragma unroll
        for (int mt = 0; mt < 2; ++mt)
#pragma unroll
            for (int h2 = 0; h2 < 2; ++h2) {
                const int row = m0 + wm * 32 + mt * 16 + g + h2 * 8;
                gemm_epilogue_elem<EPI>(row, col,
                    acc[mt][nt][h2 * 2 + 0] + bia0,
                    acc[mt][nt][h2 * 2 + 1] + bia1, N, Rres, C, Ch);
            }
    }
}

// ---------------------------------------------------------------------------
// Variant C: 256x128 CTA tile, 512 threads, 16 warps 4x4, warp tile 64x32,
// 3-stage. 2x MMA per ldsm vs variant A/B -> latency-tolerant.
// Used for LARGE grids (qkv: 192 CTAs, mlp1: 256 CTAs).
// ---------------------------------------------------------------------------
#define A_BYTES_C (256 * RSTRIDE)          // 20480
#define STG_C (A_BYTES_C + 2 * MAT_BYTES)  // 40960
#define NSTG_C 3
#define SMEM_C (NSTG_C * STG_C)            // 122880

template <int EPI>
__global__ void __launch_bounds__(512, 1) gemm_mma_big(
    const __half* __restrict__ A,
    const __half* __restrict__ Bh, const __half* __restrict__ Bl,
    const float* __restrict__ bias, const float* __restrict__ Rres,
    float* __restrict__ C, __half* __restrict__ Ch,
    int M, int N, int K)
{
    extern __shared__ char smem[];
    const uint32_t sbase = smem_u32(smem);
    const int tid = threadIdx.x, wid = tid >> 5, lane = tid & 31;
    const int m0 = blockIdx.y * 256, n0 = blockIdx.x * 128;
    const int wm = wid & 3, wn = wid >> 2;        // warp tile: 64(m) x 32(n)
    const int g = lane >> 2, q = lane & 3;
    const uint32_t aoff = (uint32_t)((wm * 64 + (lane & 15)) * RSTRIDE + (lane >> 4) * 16);
    const uint32_t boff = (uint32_t)((wn * 32 + (lane >> 4) * 8 + (lane & 7)) * RSTRIDE
                                     + ((lane >> 3) & 1) * 16);

    float acc[4][4][4];
#pragma unroll
    for (int i = 0; i < 4; ++i)
#pragma unroll
        for (int j = 0; j < 4; ++j)
#pragma unroll
            for (int r = 0; r < 4; ++r) acc[i][j][r] = 0.f;

    const int CH = K >> 5;
    auto load_stage = [&](int c, int buf) {
        const int k0 = c << 5;
        const uint32_t sbuf = sbase + buf * STG_C;
        // A: 256 rows x 4 chunks = 1024 cp.async
#pragma unroll
        for (int u = 0; u < 2; ++u) {
            const int i = tid + (u << 9);
            const int row = i >> 2, ch = i & 3;
            cp_async16(sbuf + row * RSTRIDE + ch * 16,
                       A + (size_t)(m0 + row) * K + k0 + ch * 8);
        }
        // B: 128 rows x 4 chunks, hi + lo
        {
            const int row = tid >> 2, ch = tid & 3;
            const uint32_t so = sbuf + A_BYTES_C + row * RSTRIDE + ch * 16;
            const size_t gb = (size_t)(n0 + row) * K + k0 + ch * 8;
            cp_async16(so,             Bh + gb);
            cp_async16(so + MAT_BYTES, Bl + gb);
        }
    };
    load_stage(0, 0); CP_COMMIT();
    load_stage(1, 1); CP_COMMIT();

    int cb = 0, lb = 2;
    for (int c = 0; c < CH; ++c) {
        CP_WAIT(1);
        __syncthreads();
        const uint32_t sA = sbase + cb * STG_C;
        const uint32_t sB = sA + A_BYTES_C;
#pragma unroll
        for (int ks = 0; ks < 2; ++ks) {
            uint32_t Af[4][4], Bhf[4][2], Blf[4][2];
#pragma unroll
            for (int mt = 0; mt < 4; ++mt) {
                const uint32_t aa = sA + aoff + mt * 16 * RSTRIDE + ks * 32;
                ldsm4(aa, Af[mt][0], Af[mt][1], Af[mt][2], Af[mt][3]);
            }
#pragma unroll
            for (int p = 0; p < 2; ++p) {
                const uint32_t ba = sB + boff + p * 16 * RSTRIDE + ks * 32;
                ldsm4(ba,             Bhf[2*p][0], Bhf[2*p][1], Bhf[2*p+1][0], Bhf[2*p+1][1]);
                ldsm4(ba + MAT_BYTES, Blf[2*p][0], Blf[2*p][1], Blf[2*p+1][0], Blf[2*p+1][1]);
            }
#pragma unroll
            for (int mt = 0; mt < 4; ++mt)
#pragma unroll
                for (int nt = 0; nt < 4; ++nt)
                    mma_f16(acc[mt][nt], Af[mt], Bhf[nt]);
#pragma unroll
            for (int mt = 0; mt < 4; ++mt)
#pragma unroll
                for (int nt = 0; nt < 4; ++nt)
                    mma_f16(acc[mt][nt], Af[mt], Blf[nt]);
        }
        if (c + 2 < CH) load_stage(c + 2, lb);
        CP_COMMIT();
        cb = (cb + 1 == NSTG_C) ? 0 : cb + 1;
        lb = (lb + 1 == NSTG_C) ? 0 : lb + 1;
    }

#pragma unroll
    for (int nt = 0; nt < 4; ++nt) {
        const int col = n0 + wn * 32 + nt * 8 + q * 2;
        const float bia0 = bias[col], bia1 = bias[col + 1];
#pragma unroll
        for (int mt = 0; mt < 4; ++mt)
#pragma unroll
            for (int h2 = 0; h2 < 2; ++h2) {
                const int row = m0 + wm * 64 + mt * 16 + g + h2 * 8;
                gemm_epilogue_elem<EPI>(row, col,
                    acc[mt][nt][h2 * 2 + 0] + bia0,
                    acc[mt][nt][h2 * 2 + 1] + bia1, N, Rres, C, Ch);
            }
    }
}

// ---------------------------------------------------------------------------
// Fused weight transpose + split — vectorized
// ---------------------------------------------------------------------------
__global__ void __launch_bounds__(256) transpose_split_all(
    const float* __restrict__ qkv_w, const float* __restrict__ proj_w,
    const float* __restrict__ mlp_w1, const float* __restrict__ mlp_w2)
{
    __shared__ float t[32][33];
    const int lay = blockIdx.y;
    int tt = blockIdx.x;
    const float* W; __half *Th, *Tl; int K, N;
    if (tt < 3072)      { W = qkv_w;  Th = g_wqh; Tl = g_wql; K = EMB;   N = 3 * EMB; }
    else if (tt < 4096) { W = proj_w; Th = g_wph; Tl = g_wpl; K = EMB;   N = EMB;   tt -= 3072; }
    else if (tt < 8192) { W = mlp_w1; Th = g_w1h; Tl = g_w1l; K = EMB;   N = FFDIM; tt -= 4096; }
    else                { W = mlp_w2; Th = g_w2h; Tl = g_w2l; K = FFDIM; N = EMB;   tt -= 8192; }
    const int ntx = N >> 5;
    const int n0 = (tt % ntx) * 32, k0 = (tt / ntx) * 32;
    const float* Ws = W + (size_t)lay * K * N;
    __half* Ths = Th + (size_t)lay * K * N;
    __half* Tls = Tl + (size_t)lay * K * N;
    const int tid = threadIdx.x;

#pragma unroll
    for (int u = 0; u < 4; ++u) {
        const int i = tid + u * 256;
        const int row = i >> 5, col = i & 31;
        t[row][col] = Ws[(size_t)(k0 + row) * N + n0 + col];
    }
    __syncthreads();

#pragma unroll
    for (int u = 0; u < 2; ++u) {
        const int i = tid + u * 256;
        const int ni = i >> 4, kh = i & 15;
        const float v0 = t[2 * kh][ni];
        const float v1 = t[2 * kh + 1][ni];
        __half h0, l0, h1, l1;
        split_f16(v0, h0, l0); split_f16(v1, h1, l1);
        __half2 hv; hv.x = h0; hv.y = h1;
        __half2 lv; lv.x = l0; lv.y = l1;
        const size_t o = (size_t)(n0 + ni) * K + k0 + 2 * kh;
        *(__half2*)(Ths + o) = hv;
        *(__half2*)(Tls + o) = lv;
    }
}

// ---------------------------------------------------------------------------
// Embed: 8 rows per block
// ---------------------------------------------------------------------------
__global__ void __launch_bounds__(256) embed_kernel(
    const float* __restrict__ xs, const float* __restrict__ ys,
    const float* __restrict__ w_in, const float* __restrict__ b_in)
{
    __shared__ float z[8][DIN];
    const int base = blockIdx.y * 8;
    const int tid = threadIdx.x;
#pragma unroll
    for (int u = 0; u < 2; ++u) {
        const int i = tid + u * 256;
        const int r = i >> 6, d = i & 63;
        const int row = base + r;
        const int b = row / LSEQ, l = row % LSEQ, k = l >> 1;
        float v;
        if ((l & 1) == 0) v = xs[(b * KLEN + k) * DIN + d];
        else              v = (d == 0) ? ys[b * KLEN + k] : 0.0f;
        z[r][d] = v;
    }
    __syncthreads();
    const int n = blockIdx.x * 256 + tid;
    float acc[8];
    const float bi = b_in[n];
#pragma unroll
    for (int r = 0; r < 8; ++r) acc[r] = bi;
#pragma unroll
    for (int d = 0; d < DIN; ++d) {
        const float w = w_in[d * EMB + n];
#pragma unroll
        for (int r = 0; r < 8; ++r) acc[r] = fmaf(z[r][d], w, acc[r]);
    }
#pragma unroll
    for (int r = 0; r < 8; ++r)
        g_x[(size_t)(base + r) * EMB + n] = acc[r];
}

// ---------------------------------------------------------------------------
// LayerNorm -> fp16 (single pass)
// ---------------------------------------------------------------------------
__global__ void __launch_bounds__(256) ln_kernel(
    const float* __restrict__ x,
    const float* __restrict__ s, const float* __restrict__ bb,
    __half* __restrict__ oh)
{
    __shared__ float red1[8], red2[8], stats[2];
    const int row = blockIdx.x, tid = threadIdx.x;
    const int wid = tid >> 5, lane = tid & 31;
    const float4 v = *(const float4*)(x + (size_t)row * EMB + tid * 4);
    float sum = v.x + v.y + v.z + v.w;
    float sq  = v.x * v.x + v.y * v.y + v.z * v.z + v.w * v.w;
#pragma unroll
    for (int o = 16; o; o >>= 1) {
        sum += __shfl_xor_sync(~0u, sum, o);
        sq  += __shfl_xor_sync(~0u, sq, o);
    }
    if (lane == 0) { red1[wid] = sum; red2[wid] = sq; }
    __syncthreads();
    if (tid == 0) {
        float ts = 0.f, tq = 0.f;
#pragma unroll
        for (int i = 0; i < 8; ++i) { ts += red1[i]; tq += red2[i]; }
        const float m = ts * (1.0f / EMB);
        const float var = tq * (1.0f / EMB) - m * m;
        stats[0] = m; stats[1] = rsqrtf(var + LN_EPS);
    }
    __syncthreads();
    const float m = stats[0], rstd = stats[1];
    const float4 sv = *(const float4*)(s + tid * 4);
    const float4 bv = *(const float4*)(bb + tid * 4);
    const float o0 = (v.x - m) * rstd * sv.x + bv.x;
    const float o1 = (v.y - m) * rstd * sv.y + bv.y;
    const float o2 = (v.z - m) * rstd * sv.z + bv.z;
    const float o3 = (v.w - m) * rstd * sv.w + bv.w;
    __half2 h01; h01.x = __float2half_rn(o0); h01.y = __float2half_rn(o1);
    __half2 h23; h23.x = __float2half_rn(o2); h23.y = __float2half_rn(o3);
    uint2 pk;
    pk.x = *(uint32_t*)&h01; pk.y = *(uint32_t*)&h23;
    *(uint2*)(oh + (size_t)row * EMB + tid * 4) = pk;
}

// ---------------------------------------------------------------------------
// Flash attention (unchanged, verified)
// ---------------------------------------------------------------------------
#define QRS 144
#define KRS 144
#define VRS 272
#define QB (128 * QRS)
#define KBY (128 * KRS)
#define VBY (64 * VRS)
#define KVSTAGE (2 * KBY + 2 * VBY)
#define FLASH_SMEM (2 * QB + 2 * KVSTAGE)  // 180224

__global__ void __launch_bounds__(256, 1) flash_attn()
{
    extern __shared__ char smem[];
    const uint32_t sb = smem_u32(smem);
    const int tid = threadIdx.x, wid = tid >> 5, lane = tid & 31;
    const int g = lane >> 2, q = lane & 3;
    const int bh = blockIdx.x;
    const int m0 = (7 - (int)blockIdx.y) * 128;
    const int nkt = (m0 >> 7) + 1;

    const __nv_bfloat16* Qh = g_qh + (size_t)bh * LSEQ * DHEAD;
    const __nv_bfloat16* Ql = g_ql + (size_t)bh * LSEQ * DHEAD;
    const __nv_bfloat16* Kh = g_kh + (size_t)bh * LSEQ * DHEAD;
    const __nv_bfloat16* Kl = g_kl + (size_t)bh * LSEQ * DHEAD;
    const __nv_bfloat16* Vh = g_vth + (size_t)bh * DHEAD * LSEQ;
    const __nv_bfloat16* Vl = g_vtl + (size_t)bh * DHEAD * LSEQ;

    for (int i = tid; i < 1024; i += 256) {
        const int row = i >> 3, ch = i & 7;
        const uint32_t so = sb + row * QRS + ch * 16;
        cp_async16(so,      Qh + (size_t)(m0 + row) * DHEAD + ch * 8);
        cp_async16(so + QB, Ql + (size_t)(m0 + row) * DHEAD + ch * 8);
    }
    auto load_kv = [&](int kt) {
        const int k0 = kt << 7;
        const uint32_t st = sb + 2 * QB + (kt & 1) * KVSTAGE;
        for (int i = tid; i < 1024; i += 256) {
            const int row = i >> 3, ch = i & 7;
            const uint32_t so = st + row * KRS + ch * 16;
            cp_async16(so,       Kh + (size_t)(k0 + row) * DHEAD + ch * 8);
            cp_async16(so + KBY, Kl + (size_t)(k0 + row) * DHEAD + ch * 8);
        }
        for (int i = tid; i < 1024; i += 256) {
            const int row = i >> 4, ch = i & 15;
            const uint32_t so = st + 2 * KBY + row * VRS + ch * 16;
            cp_async16(so,       Vh + (size_t)row * LSEQ + k0 + ch * 8);
            cp_async16(so + VBY, Vl + (size_t)row * LSEQ + k0 + ch * 8);
        }
    };
    load_kv(0);
    CP_COMMIT();

    const uint32_t aoff = (uint32_t)((wid * 16 + (lane & 15)) * QRS + (lane >> 4) * 16);
    const uint32_t bKoff = (uint32_t)(((lane >> 4) * 8 + (lane & 7)) * KRS + ((lane >> 3) & 1) * 16);
    const uint32_t bVoff = (uint32_t)(((lane >> 4) * 8 + (lane & 7)) * VRS + ((lane >> 3) & 1) * 16);

    float mrow[2] = {-1e30f, -1e30f};
    float lrow[2] = {0.f, 0.f};
    float Oa[8][4];
#pragma unroll
    for (int i = 0; i < 8; ++i)
#pragma unroll
        for (int j = 0; j < 4; ++j) Oa[i][j] = 0.f;

    for (int kt = 0; kt < nkt; ++kt) {
        if (kt + 1 < nkt) load_kv(kt + 1);
        CP_COMMIT();
        CP_WAIT(1);
        __syncthreads();

        const uint32_t st = sb + 2 * QB + (kt & 1) * KVSTAGE;
        float sacc[16][4];
#pragma unroll
        for (int i = 0; i < 16; ++i)
#pragma unroll
            for (int j = 0; j < 4; ++j) sacc[i][j] = 0.f;

#pragma unroll
        for (int ks = 0; ks < 4; ++ks) {
            uint32_t Qf[4], Qg[4];
            ldsm4(sb + aoff + ks * 32,      Qf[0], Qf[1], Qf[2], Qf[3]);
            ldsm4(sb + QB + aoff + ks * 32, Qg[0], Qg[1], Qg[2], Qg[3]);
#pragma unroll
            for (int p = 0; p < 8; ++p) {
                uint32_t bh2[2][2], bl2[2][2];
                ldsm4(st + bKoff + p * 16 * KRS + ks * 32,
                      bh2[0][0], bh2[0][1], bh2[1][0], bh2[1][1]);
                ldsm4(st + KBY + bKoff + p * 16 * KRS + ks * 32,
                      bl2[0][0], bl2[0][1], bl2[1][0], bl2[1][1]);
                mma_bf16(sacc[2*p],   Qf, bh2[0]);
                mma_bf16(sacc[2*p+1], Qf, bh2[1]);
                mma_bf16(sacc[2*p],   Qf, bl2[0]);
                mma_bf16(sacc[2*p+1], Qf, bl2[1]);
                mma_bf16(sacc[2*p],   Qg, bh2[0]);
                mma_bf16(sacc[2*p+1], Qg, bh2[1]);
            }
        }

        if (kt == nkt - 1) {
            const int rl0 = wid * 16 + g;
#pragma unroll
            for (int nt = 0; nt < 16; ++nt) {
                const int c0 = nt * 8 + q * 2;
                if (c0 > rl0)         sacc[nt][0] = -1e30f;
                if (c0 + 1 > rl0)     sacc[nt][1] = -1e30f;
                if (c0 > rl0 + 8)     sacc[nt][2] = -1e30f;
                if (c0 + 1 > rl0 + 8) sacc[nt][3] = -1e30f;
            }
        }

#pragma unroll
        for (int r = 0; r < 2; ++r) {
            float mx = -1e30f;
#pragma unroll
            for (int nt = 0; nt < 16; ++nt)
                mx = fmaxf(mx, fmaxf(sacc[nt][2*r], sacc[nt][2*r+1]));
            mx = fmaxf(mx, __shfl_xor_sync(~0u, mx, 1));
            mx = fmaxf(mx, __shfl_xor_sync(~0u, mx, 2));
            mx *= 0.125f;
            const float mnew = fmaxf(mrow[r], mx);
            const float alpha = __expf(mrow[r] - mnew);
            mrow[r] = mnew;
            float ls = 0.f;
#pragma unroll
            for (int nt = 0; nt < 16; ++nt) {
                float p0 = __expf(fmaf(sacc[nt][2*r], 0.125f, -mnew));
                float p1 = __expf(fmaf(sacc[nt][2*r+1], 0.125f, -mnew));
                sacc[nt][2*r] = p0; sacc[nt][2*r+1] = p1;
                ls += p0 + p1;
            }
            lrow[r] = lrow[r] * alpha + ls;
#pragma unroll
            for (int nt = 0; nt < 8; ++nt) {
                Oa[nt][2*r] *= alpha; Oa[nt][2*r+1] *= alpha;
            }
        }

#pragma unroll
        for (int ks = 0; ks < 8; ++ks) {
            uint32_t Ph[4], Pl[4];
            split_pack(sacc[2*ks][0],   sacc[2*ks][1],   Ph[0], Pl[0]);
            split_pack(sacc[2*ks][2],   sacc[2*ks][3],   Ph[1], Pl[1]);
            split_pack(sacc[2*ks+1][0], sacc[2*ks+1][1], Ph[2], Pl[2]);
            split_pack(sacc[2*ks+1][2], sacc[2*ks+1][3], Ph[3], Pl[3]);
#pragma unroll
            for (int p = 0; p < 4; ++p) {
                uint32_t vh2[2][2], vl2[2][2];
                ldsm4(st + 2 * KBY + bVoff + p * 16 * VRS + ks * 32,
                      vh2[0][0], vh2[0][1], vh2[1][0], vh2[1][1]);
                ldsm4(st + 2 * KBY + VBY + bVoff + p * 16 * VRS + ks * 32,
                      vl2[0][0], vl2[0][1], vl2[1][0], vl2[1][1]);
                mma_bf16(Oa[2*p],   Ph, vh2[0]);
                mma_bf16(Oa[2*p+1], Ph, vh2[1]);
                mma_bf16(Oa[2*p],   Ph, vl2[0]);
                mma_bf16(Oa[2*p+1], Ph, vl2[1]);
                mma_bf16(Oa[2*p],   Pl, vh2[0]);
                mma_bf16(Oa[2*p+1], Pl, vh2[1]);
            }
        }
        __syncthreads();
    }

    const int b = bh >> 4, hh = bh & 15;
#pragma unroll
    for (int r = 0; r < 2; ++r) {
        float l = lrow[r];
        l += __shfl_xor_sync(~0u, l, 1);
        l += __shfl_xor_sync(~0u, l, 2);
        const float inv = 1.0f / l;
        const int row = m0 + wid * 16 + g + r * 8;
#pragma unroll
        for (int nt = 0; nt < 8; ++nt) {
            __half2 hv;
            hv.x = __float2half_rn(Oa[nt][2*r] * inv);
            hv.y = __float2half_rn(Oa[nt][2*r+1] * inv);
            *(__half2*)(g_a + ((size_t)(b * LSEQ + row)) * EMB
                        + hh * DHEAD + nt * 8 + q * 2) = hv;
        }
    }
}

// ---------------------------------------------------------------------------
// Head
// ---------------------------------------------------------------------------
__global__ void head_kernel(const float* __restrict__ x, const float* __restrict__ w_out,
                            const float* __restrict__ b_out, float* __restrict__ out)
{
    __shared__ float red[256];
    const int idx = blockIdx.x, b = idx / KLEN, k = idx % KLEN, tid = threadIdx.x;
    const float* xr = x + ((size_t)(b * LSEQ + 2 * k)) * EMB;
    float acc = 0.f;
#pragma unroll
    for (int c = tid; c < EMB; c += 256) acc = fmaf(xr[c], w_out[c], acc);
    red[tid] = acc;
    __syncthreads();
    for (int off = 128; off > 0; off >>= 1) {
        if (tid < off) red[tid] += red[tid + off];
        __syncthreads();
    }
    if (tid == 0) out[idx] = red[0] + b_out[0];
}

// ---------------------------------------------------------------------------
// Launch
// ---------------------------------------------------------------------------
extern "C" void kernel_launch(void* const* d_in, const int* in_sizes, int n_in,
                              void* d_out, int out_size)
{
    const float* xs     = (const float*)d_in[0];
    const float* ys     = (const float*)d_in[1];
    const float* w_in   = (const float*)d_in[2];
    const float* b_in   = (const float*)d_in[3];
    const float* qkv_w  = (const float*)d_in[4];
    const float* qkv_b  = (const float*)d_in[5];
    const float* proj_w = (const float*)d_in[6];
    const float* proj_b = (const float*)d_in[7];
    const float* ln1_s  = (const float*)d_in[8];
    const float* ln1_b  = (const float*)d_in[9];
    const float* ln2_s  = (const float*)d_in[10];
    const float* ln2_b  = (const float*)d_in[11];
    const float* mlp_w1 = (const float*)d_in[12];
    const float* mlp_b1 = (const float*)d_in[13];
    const float* mlp_w2 = (const float*)d_in[14];
    const float* mlp_b2 = (const float*)d_in[15];
    const float* w_out  = (const float*)d_in[16];
    const float* b_out  = (const float*)d_in[17];
    float* out = (float*)d_out;

    float* x;
    __half *hbuf, *abuf, *fbuf;
    __half *wqh, *wql, *wph, *wpl, *w1h, *w1l, *w2h, *w2l;
    cudaGetSymbolAddress((void**)&x,    g_x);
    cudaGetSymbolAddress((void**)&hbuf, g_h);
    cudaGetSymbolAddress((void**)&abuf, g_a);
    cudaGetSymbolAddress((void**)&fbuf, g_f);
    cudaGetSymbolAddress((void**)&wqh, g_wqh); cudaGetSymbolAddress((void**)&wql, g_wql);
    cudaGetSymbolAddress((void**)&wph, g_wph); cudaGetSymbolAddress((void**)&wpl, g_wpl);
    cudaGetSymbolAddress((void**)&w1h, g_w1h); cudaGetSymbolAddress((void**)&w1l, g_w1l);
    cudaGetSymbolAddress((void**)&w2h, g_w2h); cudaGetSymbolAddress((void**)&w2l, g_w2l);

    cudaFuncSetAttribute(gemm_mma512<1>,  cudaFuncAttributeMaxDynamicSharedMemorySize, SMEM_A);
    cudaFuncSetAttribute(gemm_mma_big<0>, cudaFuncAttributeMaxDynamicSharedMemorySize, SMEM_C);
    cudaFuncSetAttribute(gemm_mma_big<2>, cudaFuncAttributeMaxDynamicSharedMemorySize, SMEM_C);
    cudaFuncSetAttribute(flash_attn,      cudaFuncAttributeMaxDynamicSharedMemorySize, FLASH_SMEM);

    const int M = MROWS;

    transpose_split_all<<<dim3(12288, NLAYER), 256>>>(qkv_w, proj_w, mlp_w1, mlp_w2);
    embed_kernel<<<dim3(EMB / 256, M / 8), 256>>>(xs, ys, w_in, b_in);

    for (int lay = 0; lay < NLAYER; ++lay) {
        const float* qb  = qkv_b  + (size_t)lay * 3 * EMB;
        const float* pb  = proj_b + (size_t)lay * EMB;
        const float* s1  = ln1_s  + (size_t)lay * EMB;
        const float* c1  = ln1_b  + (size_t)lay * EMB;
        const float* s2  = ln2_s  + (size_t)lay * EMB;
        const float* c2  = ln2_b  + (size_t)lay * EMB;
        const float* bb1 = mlp_b1 + (size_t)lay * FFDIM;
        const float* bb2 = mlp_b2 + (size_t)lay * EMB;
        const __half* lwqh = wqh + (size_t)lay * 3 * EMB * EMB;
        const __half* lwql = wql + (size_t)lay * 3 * EMB * EMB;
        const __half* lwph = wph + (size_t)lay * EMB * EMB;
        const __half* lwpl = wpl + (size_t)lay * EMB * EMB;
        const __half* lw1h = w1h + (size_t)lay * FFDIM * EMB;
        const __half* lw1l = w1l + (size_t)lay * FFDIM * EMB;
        const __half* lw2h = w2h + (size_t)lay * EMB * FFDIM;
        const __half* lw2l = w2l + (size_t)lay * EMB * FFDIM;

        ln_kernel<<<M, 256>>>(x, s1, c1, hbuf);
        // qkv: 256x128 tiles -> grid (24, 8) = 192 CTAs
        gemm_mma_big<0><<<dim3(3 * EMB / 128, M / 256), 512, SMEM_C>>>(
            hbuf, lwqh, lwql, qb, nullptr, nullptr, nullptr, M, 3 * EMB, EMB);
        flash_attn<<<dim3(NBH, 8), 256, FLASH_SMEM>>>();
        // proj: small grid -> 128x128 512-thread variant
        gemm_mma512<1><<<dim3(EMB / 128, M / 128), 512, SMEM_A>>>(
            abuf, lwph, lwpl, pb, x, x, nullptr, M, EMB, EMB);
        ln_kernel<<<M, 256>>>(x, s2, c2, hbuf);
        // mlp1: 256x128 tiles -> grid (32, 8) = 256 CTAs
        gemm_mma_big<2><<<dim3(FFDIM / 128, M / 256), 512, SMEM_C>>>(
            hbuf, lw1h, lw1l, bb1, nullptr, nullptr, fbuf, M, FFDIM, EMB);
        // mlp2: small grid -> 128x128 512-thread variant
        gemm_mma512<1><<<dim3(EMB / 128, M / 128), 512, SMEM_A>>>(
            fbuf, lw2h, lw2l, bb2, x, x, nullptr, M, EMB, FFDIM);
    }

    head_kernel<<<BATCH * KLEN, 256>>>(x, w_out, b_out, out);
}

// round 14
// speedup vs baseline: 1.0121x; 1.0121x over previous
#include <cuda_runtime.h>
#include <cuda_fp16.h>
#include <cuda_bf16.h>
#include <math.h>
#include <stdint.h>

#define BATCH 2
#define KLEN  512
#define LSEQ  1024
#define EMB   1024
#define NHEAD 16
#define DHEAD 64
#define NLAYER 12
#define FFDIM 4096
#define DIN   64
#define LN_EPS 1e-5f
#define MROWS (BATCH * LSEQ)   // 2048
#define NBH   (BATCH * NHEAD)  // 32

// ---------------------------------------------------------------------------
// Scratch (device globals; zero-initialized; allocation forbidden)
// ---------------------------------------------------------------------------
__device__ float g_x [MROWS * EMB];
__device__ __half g_h[MROWS * EMB];
__device__ __half g_a[MROWS * EMB];
__device__ __half g_f[MROWS * FFDIM];
__device__ __nv_bfloat16 g_qh[NBH * LSEQ * DHEAD];
__device__ __nv_bfloat16 g_ql[NBH * LSEQ * DHEAD];
__device__ __nv_bfloat16 g_kh[NBH * LSEQ * DHEAD];
__device__ __nv_bfloat16 g_kl[NBH * LSEQ * DHEAD];
__device__ __nv_bfloat16 g_vth[NBH * DHEAD * LSEQ];
__device__ __nv_bfloat16 g_vtl[NBH * DHEAD * LSEQ];
__device__ __half g_wqh[NLAYER * 3 * EMB * EMB];
__device__ __half g_wql[NLAYER * 3 * EMB * EMB];
__device__ __half g_wph[NLAYER * EMB * EMB];
__device__ __half g_wpl[NLAYER * EMB * EMB];
__device__ __half g_w1h[NLAYER * FFDIM * EMB];
__device__ __half g_w1l[NLAYER * FFDIM * EMB];
__device__ __half g_w2h[NLAYER * EMB * FFDIM];
__device__ __half g_w2l[NLAYER * EMB * FFDIM];

// ---------------------------------------------------------------------------
// Helpers
// ---------------------------------------------------------------------------
__device__ __forceinline__ uint32_t smem_u32(const void* p) {
    uint32_t a;
    asm("{ .reg .u64 t; cvta.to.shared.u64 t, %1; cvt.u32.u64 %0, t; }" : "=r"(a) : "l"(p));
    return a;
}
__device__ __forceinline__ void cp_async16(uint32_t s, const void* g) {
    asm volatile("cp.async.cg.shared.global [%0], [%1], 16;" :: "r"(s), "l"(g));
}
#define CP_COMMIT() asm volatile("cp.async.commit_group;" ::: "memory")
#define CP_WAIT(n)  asm volatile("cp.async.wait_group %0;" :: "n"(n) : "memory")

__device__ __forceinline__ void ldsm4(uint32_t a, uint32_t& r0, uint32_t& r1,
                                      uint32_t& r2, uint32_t& r3) {
    asm volatile("ldmatrix.sync.aligned.m8n8.x4.shared.b16 {%0,%1,%2,%3}, [%4];"
                 : "=r"(r0), "=r"(r1), "=r"(r2), "=r"(r3) : "r"(a));
}
__device__ __forceinline__ void mma_f16(float* d, const uint32_t* a, const uint32_t* b) {
    asm volatile(
        "mma.sync.aligned.m16n8k16.row.col.f32.f16.f16.f32 "
        "{%0,%1,%2,%3}, {%4,%5,%6,%7}, {%8,%9}, {%0,%1,%2,%3};"
        : "+f"(d[0]), "+f"(d[1]), "+f"(d[2]), "+f"(d[3])
        : "r"(a[0]), "r"(a[1]), "r"(a[2]), "r"(a[3]), "r"(b[0]), "r"(b[1]));
}
__device__ __forceinline__ void mma_bf16(float* d, const uint32_t* a, const uint32_t* b) {
    asm volatile(
        "mma.sync.aligned.m16n8k16.row.col.f32.bf16.bf16.f32 "
        "{%0,%1,%2,%3}, {%4,%5,%6,%7}, {%8,%9}, {%0,%1,%2,%3};"
        : "+f"(d[0]), "+f"(d[1]), "+f"(d[2]), "+f"(d[3])
        : "r"(a[0]), "r"(a[1]), "r"(a[2]), "r"(a[3]), "r"(b[0]), "r"(b[1]));
}
__device__ __forceinline__ void split_f16(float v, __half& hi, __half& lo) {
    hi = __float2half_rn(v);
    lo = __float2half_rn(v - __half2float(hi));
}
__device__ __forceinline__ void split_bf(float v, __nv_bfloat16& hi, __nv_bfloat16& lo) {
    hi = __float2bfloat16(v);
    lo = __float2bfloat16(v - __bfloat162float(hi));
}
__device__ __forceinline__ void split_pack(float v0, float v1, uint32_t& ph, uint32_t& pl) {
    asm("cvt.rn.bf16x2.f32 %0, %1, %2;" : "=r"(ph) : "f"(v1), "f"(v0));
    float h0 = __uint_as_float(ph << 16);
    float h1 = __uint_as_float(ph & 0xFFFF0000u);
    float r0 = v0 - h0, r1 = v1 - h1;
    asm("cvt.rn.bf16x2.f32 %0, %1, %2;" : "=r"(pl) : "f"(r1), "f"(r0));
}

// ---------------------------------------------------------------------------
// Epilogue (shared)
// ---------------------------------------------------------------------------
template <int EPI>
__device__ __forceinline__ void gemm_epilogue_elem(
    int row, int col, float v0, float v1, int N,
    const float* __restrict__ Rres, float* __restrict__ C, __half* __restrict__ Ch)
{
    if (EPI == 0) {
        const int b = row >> 10, l = row & 1023;
        const int part = col >> 10;
        const int h = (col & 1023) >> 6, d = col & 63;
        const int bh = b * NHEAD + h;
        __nv_bfloat16 h0, l0, h1, l1;
        split_bf(v0, h0, l0); split_bf(v1, h1, l1);
        if (part == 2) {
            const size_t o = ((size_t)bh * DHEAD + d) * LSEQ + l;
            g_vth[o] = h0; g_vtl[o] = l0;
            g_vth[o + LSEQ] = h1; g_vtl[o + LSEQ] = l1;
        } else {
            const size_t o = ((size_t)bh * LSEQ + l) * DHEAD + d;
            __nv_bfloat162 hv; hv.x = h0; hv.y = h1;
            __nv_bfloat162 lv; lv.x = l0; lv.y = l1;
            if (part == 0) {
                *(__nv_bfloat162*)(g_qh + o) = hv;
                *(__nv_bfloat162*)(g_ql + o) = lv;
            } else {
                *(__nv_bfloat162*)(g_kh + o) = hv;
                *(__nv_bfloat162*)(g_kl + o) = lv;
            }
        }
    } else {
        const size_t o = (size_t)row * N + col;
        if (EPI == 1) {
            v0 += Rres[o]; v1 += Rres[o + 1];
            float2 fv = {v0, v1}; *(float2*)(C + o) = fv;
        } else {
            v0 = 0.5f * v0 * (1.0f + erff(v0 * 0.70710678118654752f));
            v1 = 0.5f * v1 * (1.0f + erff(v1 * 0.70710678118654752f));
            __half2 hv; hv.x = __float2half_rn(v0); hv.y = __float2half_rn(v1);
            *(__half2*)(Ch + o) = hv;
        }
    }
}

// ---------------------------------------------------------------------------
// Variant A: 128x128 tile, 512 threads, 16 warps 4x4, warp 32x32, 4-stage.
// SMALL grids (proj, mlp2: 128 CTAs).
// ---------------------------------------------------------------------------
#define RSTRIDE 80
#define MAT_BYTES (128 * RSTRIDE)
#define STG_A (3 * MAT_BYTES)
#define NSTG_A 4
#define SMEM_A (NSTG_A * STG_A)            // 122880

template <int EPI>
__global__ void __launch_bounds__(512, 1) gemm_mma512(
    const __half* __restrict__ A,
    const __half* __restrict__ Bh, const __half* __restrict__ Bl,
    const float* __restrict__ bias, const float* __restrict__ Rres,
    float* __restrict__ C, __half* __restrict__ Ch,
    int M, int N, int K)
{
    extern __shared__ char smem[];
    const uint32_t sbase = smem_u32(smem);
    const int tid = threadIdx.x, wid = tid >> 5, lane = tid & 31;
    const int m0 = blockIdx.y * 128, n0 = blockIdx.x * 128;
    const int wm = wid & 3, wn = wid >> 2;
    const int g = lane >> 2, q = lane & 3;
    const int lrow = tid >> 2, lch = tid & 3;
    const uint32_t soff = (uint32_t)(lrow * RSTRIDE + lch * 16);
    const uint32_t aoff = (uint32_t)((wm * 32 + (lane & 15)) * RSTRIDE + (lane >> 4) * 16);
    const uint32_t boff = (uint32_t)((wn * 32 + (lane >> 4) * 8 + (lane & 7)) * RSTRIDE
                                     + ((lane >> 3) & 1) * 16);

    float acc[2][4][4];
#pragma unroll
    for (int i = 0; i < 2; ++i)
#pragma unroll
        for (int j = 0; j < 4; ++j)
#pragma unroll
            for (int r = 0; r < 4; ++r) acc[i][j][r] = 0.f;

    const int CH = K >> 5;
    auto load_stage = [&](int c) {
        const int k0 = c << 5;
        const uint32_t sb = sbase + (c & (NSTG_A - 1)) * STG_A + soff;
        const size_t ga = (size_t)(m0 + lrow) * K + k0 + lch * 8;
        const size_t gb = (size_t)(n0 + lrow) * K + k0 + lch * 8;
        cp_async16(sb,                 A  + ga);
        cp_async16(sb + MAT_BYTES,     Bh + gb);
        cp_async16(sb + 2 * MAT_BYTES, Bl + gb);
    };
    load_stage(0); CP_COMMIT();
    load_stage(1); CP_COMMIT();
    load_stage(2); CP_COMMIT();

    for (int c = 0; c < CH; ++c) {
        CP_WAIT(2);
        __syncthreads();
        const uint32_t sA = sbase + (c & (NSTG_A - 1)) * STG_A;
        const uint32_t sB = sA + MAT_BYTES;
#pragma unroll
        for (int ks = 0; ks < 2; ++ks) {
            uint32_t Af[2][4], Bhf[4][2], Blf[4][2];
#pragma unroll
            for (int mt = 0; mt < 2; ++mt) {
                const uint32_t aa = sA + aoff + mt * 16 * RSTRIDE + ks * 32;
                ldsm4(aa, Af[mt][0], Af[mt][1], Af[mt][2], Af[mt][3]);
            }
#pragma unroll
            for (int p = 0; p < 2; ++p) {
                const uint32_t ba = sB + boff + p * 16 * RSTRIDE + ks * 32;
                ldsm4(ba,             Bhf[2*p][0], Bhf[2*p][1], Bhf[2*p+1][0], Bhf[2*p+1][1]);
                ldsm4(ba + MAT_BYTES, Blf[2*p][0], Blf[2*p][1], Blf[2*p+1][0], Blf[2*p+1][1]);
            }
#pragma unroll
            for (int mt = 0; mt < 2; ++mt)
#pragma unroll
                for (int nt = 0; nt < 4; ++nt)
                    mma_f16(acc[mt][nt], Af[mt], Bhf[nt]);
#pragma unroll
            for (int mt = 0; mt < 2; ++mt)
#pragma unroll
                for (int nt = 0; nt < 4; ++nt)
                    mma_f16(acc[mt][nt], Af[mt], Blf[nt]);
        }
        if (c + 3 < CH) load_stage(c + 3);
        CP_COMMIT();
    }

#pragma unroll
    for (int nt = 0; nt < 4; ++nt) {
        const int col = n0 + wn * 32 + nt * 8 + q * 2;
        const float bia0 = bias[col], bia1 = bias[col + 1];
#pragma unroll
        for (int mt = 0; mt < 2; ++mt)
#pragma unroll
            for (int h2 = 0; h2 < 2; ++h2) {
                const int row = m0 + wm * 32 + mt * 16 + g + h2 * 8;
                gemm_epilogue_elem<EPI>(row, col,
                    acc[mt][nt][h2 * 2 + 0] + bia0,
                    acc[mt][nt][h2 * 2 + 1] + bia1, N, Rres, C, Ch);
            }
    }
}

// ---------------------------------------------------------------------------
// Variant B: 256 threads, 8 warps 2x4, warp tile 64x32, 3-stage, 2 CTA/SM.
// LARGE grids (qkv: 384 CTAs, mlp1: 512 CTAs).
// ---------------------------------------------------------------------------
#define STG_B (3 * MAT_BYTES)              // 30720
#define NSTG_B 3
#define SMEM_B (NSTG_B * STG_B)            // 92160

template <int EPI>
__global__ void __launch_bounds__(256, 2) gemm_mma256(
    const __half* __restrict__ A,
    const __half* __restrict__ Bh, const __half* __restrict__ Bl,
    const float* __restrict__ bias, const float* __restrict__ Rres,
    float* __restrict__ C, __half* __restrict__ Ch,
    int M, int N, int K)
{
    extern __shared__ char smem[];
    const uint32_t sbase = smem_u32(smem);
    const int tid = threadIdx.x, wid = tid >> 5, lane = tid & 31;
    const int m0 = blockIdx.y * 128, n0 = blockIdx.x * 128;
    const int wm = wid & 1, wn = wid >> 1;
    const int g = lane >> 2, q = lane & 3;
    const uint32_t aoff = (uint32_t)((wm * 64 + (lane & 15)) * RSTRIDE + (lane >> 4) * 16);
    const uint32_t boff = (uint32_t)((wn * 32 + (lane >> 4) * 8 + (lane & 7)) * RSTRIDE
                                     + ((lane >> 3) & 1) * 16);

    float acc[4][4][4];
#pragma unroll
    for (int i = 0; i < 4; ++i)
#pragma unroll
        for (int j = 0; j < 4; ++j)
#pragma unroll
            for (int r = 0; r < 4; ++r) acc[i][j][r] = 0.f;

    const int CH = K >> 5;
    auto load_stage = [&](int c, int buf) {
        const int k0 = c << 5;
        const uint32_t sbuf = sbase + buf * STG_B;
#pragma unroll
        for (int u = 0; u < 2; ++u) {
            const int i = tid + (u << 8);
            const int row = i >> 2, ch = i & 3;
            const uint32_t so = sbuf + row * RSTRIDE + ch * 16;
            const size_t ga = (size_t)(m0 + row) * K + k0 + ch * 8;
            const size_t gb = (size_t)(n0 + row) * K + k0 + ch * 8;
            cp_async16(so,                 A  + ga);
            cp_async16(so + MAT_BYTES,     Bh + gb);
            cp_async16(so + 2 * MAT_BYTES, Bl + gb);
        }
    };
    load_stage(0, 0); CP_COMMIT();
    load_stage(1, 1); CP_COMMIT();

    int cb = 0, lb = 2;
    for (int c = 0; c < CH; ++c) {
        CP_WAIT(1);
        __syncthreads();
        const uint32_t sA = sbase + cb * STG_B;
        const uint32_t sB = sA + MAT_BYTES;
#pragma unroll
        for (int ks = 0; ks < 2; ++ks) {
            uint32_t Af[4][4], Bhf[4][2], Blf[4][2];
#pragma unroll
            for (int mt = 0; mt < 4; ++mt) {
                const uint32_t aa = sA + aoff + mt * 16 * RSTRIDE + ks * 32;
                ldsm4(aa, Af[mt][0], Af[mt][1], Af[mt][2], Af[mt][3]);
            }
#pragma unroll
            for (int p = 0; p < 2; ++p) {
                const uint32_t ba = sB + boff + p * 16 * RSTRIDE + ks * 32;
                ldsm4(ba,             Bhf[2*p][0], Bhf[2*p][1], Bhf[2*p+1][0], Bhf[2*p+1][1]);
                ldsm4(ba + MAT_BYTES, Blf[2*p][0], Blf[2*p][1], Blf[2*p+1][0], Blf[2*p+1][1]);
            }
#pragma unroll
            for (int mt = 0; mt < 4; ++mt)
#pragma unroll
                for (int nt = 0; nt < 4; ++nt)
                    mma_f16(acc[mt][nt], Af[mt], Bhf[nt]);
#pragma unroll
            for (int mt = 0; mt < 4; ++mt)
#pragma unroll
                for (int nt = 0; nt < 4; ++nt)
                    mma_f16(acc[mt][nt], Af[mt], Blf[nt]);
        }
        if (c + 2 < CH) load_stage(c + 2, lb);
        CP_COMMIT();
        cb = (cb + 1 == NSTG_B) ? 0 : cb + 1;
        lb = (lb + 1 == NSTG_B) ? 0 : lb + 1;
    }

#pragma unroll
    for (int nt = 0; nt < 4; ++nt) {
        const int col = n0 + wn * 32 + nt * 8 + q * 2;
        const float bia0 = bias[col], bia1 = bias[col + 1];
#pragma unroll
        for (int mt = 0; mt < 4; ++mt)
#pragma unroll
            for (int h2 = 0; h2 < 2; ++h2) {
                const int row = m0 + wm * 64 + mt * 16 + g + h2 * 8;
                gemm_epilogue_elem<EPI>(row, col,
                    acc[mt][nt][h2 * 2 + 0] + bia0,
                    acc[mt][nt][h2 * 2 + 1] + bia1, N, Rres, C, Ch);
            }
    }
}

// ---------------------------------------------------------------------------
// Fused weight transpose + split — vectorized
// ---------------------------------------------------------------------------
__global__ void __launch_bounds__(256) transpose_split_all(
    const float* __restrict__ qkv_w, const float* __restrict__ proj_w,
    const float* __restrict__ mlp_w1, const float* __restrict__ mlp_w2)
{
    __shared__ float t[32][33];
    const int lay = blockIdx.y;
    int tt = blockIdx.x;
    const float* W; __half *Th, *Tl; int K, N;
    if (tt < 3072)      { W = qkv_w;  Th = g_wqh; Tl = g_wql; K = EMB;   N = 3 * EMB; }
    else if (tt < 4096) { W = proj_w; Th = g_wph; Tl = g_wpl; K = EMB;   N = EMB;   tt -= 3072; }
    else if (tt < 8192) { W = mlp_w1; Th = g_w1h; Tl = g_w1l; K = EMB;   N = FFDIM; tt -= 4096; }
    else                { W = mlp_w2; Th = g_w2h; Tl = g_w2l; K = FFDIM; N = EMB;   tt -= 8192; }
    const int ntx = N >> 5;
    const int n0 = (tt % ntx) * 32, k0 = (tt / ntx) * 32;
    const float* Ws = W + (size_t)lay * K * N;
    __half* Ths = Th + (size_t)lay * K * N;
    __half* Tls = Tl + (size_t)lay * K * N;
    const int tid = threadIdx.x;

#pragma unroll
    for (int u = 0; u < 4; ++u) {
        const int i = tid + u * 256;
        const int row = i >> 5, col = i & 31;
        t[row][col] = Ws[(size_t)(k0 + row) * N + n0 + col];
    }
    __syncthreads();

#pragma unroll
    for (int u = 0; u < 2; ++u) {
        const int i = tid + u * 256;
        const int ni = i >> 4, kh = i & 15;
        const float v0 = t[2 * kh][ni];
        const float v1 = t[2 * kh + 1][ni];
        __half h0, l0, h1, l1;
        split_f16(v0, h0, l0); split_f16(v1, h1, l1);
        __half2 hv; hv.x = h0; hv.y = h1;
        __half2 lv; lv.x = l0; lv.y = l1;
        const size_t o = (size_t)(n0 + ni) * K + k0 + 2 * kh;
        *(__half2*)(Ths + o) = hv;
        *(__half2*)(Tls + o) = lv;
    }
}

// ---------------------------------------------------------------------------
// Embed: 8 rows per block
// ---------------------------------------------------------------------------
__global__ void __launch_bounds__(256) embed_kernel(
    const float* __restrict__ xs, const float* __restrict__ ys,
    const float* __restrict__ w_in, const float* __restrict__ b_in)
{
    __shared__ float z[8][DIN];
    const int base = blockIdx.y * 8;
    const int tid = threadIdx.x;
#pragma unroll
    for (int u = 0; u < 2; ++u) {
        const int i = tid + u * 256;
        const int r = i >> 6, d = i & 63;
        const int row = base + r;
        const int b = row / LSEQ, l = row % LSEQ, k = l >> 1;
        float v;
        if ((l & 1) == 0) v = xs[(b * KLEN + k) * DIN + d];
        else              v = (d == 0) ? ys[b * KLEN + k] : 0.0f;
        z[r][d] = v;
    }
    __syncthreads();
    const int n = blockIdx.x * 256 + tid;
    float acc[8];
    const float bi = b_in[n];
#pragma unroll
    for (int r = 0; r < 8; ++r) acc[r] = bi;
#pragma unroll
    for (int d = 0; d < DIN; ++d) {
        const float w = w_in[d * EMB + n];
#pragma unroll
        for (int r = 0; r < 8; ++r) acc[r] = fmaf(z[r][d], w, acc[r]);
    }
#pragma unroll
    for (int r = 0; r < 8; ++r)
        g_x[(size_t)(base + r) * EMB + n] = acc[r];
}

// ---------------------------------------------------------------------------
// LayerNorm -> fp16 (single pass)
// ---------------------------------------------------------------------------
__global__ void __launch_bounds__(256) ln_kernel(
    const float* __restrict__ x,
    const float* __restrict__ s, const float* __restrict__ bb,
    __half* __restrict__ oh)
{
    __shared__ float red1[8], red2[8], stats[2];
    const int row = blockIdx.x, tid = threadIdx.x;
    const int wid = tid >> 5, lane = tid & 31;
    const float4 v = *(const float4*)(x + (size_t)row * EMB + tid * 4);
    float sum = v.x + v.y + v.z + v.w;
    float sq  = v.x * v.x + v.y * v.y + v.z * v.z + v.w * v.w;
#pragma unroll
    for (int o = 16; o; o >>= 1) {
        sum += __shfl_xor_sync(~0u, sum, o);
        sq  += __shfl_xor_sync(~0u, sq, o);
    }
    if (lane == 0) { red1[wid] = sum; red2[wid] = sq; }
    __syncthreads();
    if (tid == 0) {
        float ts = 0.f, tq = 0.f;
#pragma unroll
        for (int i = 0; i < 8; ++i) { ts += red1[i]; tq += red2[i]; }
        const float m = ts * (1.0f / EMB);
        const float var = tq * (1.0f / EMB) - m * m;
        stats[0] = m; stats[1] = rsqrtf(var + LN_EPS);
    }
    __syncthreads();
    const float m = stats[0], rstd = stats[1];
    const float4 sv = *(const float4*)(s + tid * 4);
    const float4 bv = *(const float4*)(bb + tid * 4);
    const float o0 = (v.x - m) * rstd * sv.x + bv.x;
    const float o1 = (v.y - m) * rstd * sv.y + bv.y;
    const float o2 = (v.z - m) * rstd * sv.z + bv.z;
    const float o3 = (v.w - m) * rstd * sv.w + bv.w;
    __half2 h01; h01.x = __float2half_rn(o0); h01.y = __float2half_rn(o1);
    __half2 h23; h23.x = __float2half_rn(o2); h23.y = __float2half_rn(o3);
    uint2 pk;
    pk.x = *(uint32_t*)&h01; pk.y = *(uint32_t*)&h23;
    *(uint2*)(oh + (size_t)row * EMB + tid * 4) = pk;
}

// ---------------------------------------------------------------------------
// Flash attention: single-buffered KV, 2 CTAs/SM (cross-CTA latency hiding).
// One CTA per (bh, 128-query block). 256 threads = 8 warps.
// ---------------------------------------------------------------------------
#define QRS 144
#define KRS 144
#define VRS 272
#define QB (128 * QRS)
#define KBY (128 * KRS)
#define VBY (64 * VRS)
#define KVSTAGE (2 * KBY + 2 * VBY)        // 71680
#define FLASH_SMEM (2 * QB + KVSTAGE)      // 108544 (x2 CTAs = 217088 <= 228KB)

__global__ void __launch_bounds__(256, 2) flash_attn()
{
    extern __shared__ char smem[];
    const uint32_t sb = smem_u32(smem);
    const int tid = threadIdx.x, wid = tid >> 5, lane = tid & 31;
    const int g = lane >> 2, q = lane & 3;
    const int bh = blockIdx.x;
    const int m0 = (7 - (int)blockIdx.y) * 128;
    const int nkt = (m0 >> 7) + 1;

    const __nv_bfloat16* Qh = g_qh + (size_t)bh * LSEQ * DHEAD;
    const __nv_bfloat16* Ql = g_ql + (size_t)bh * LSEQ * DHEAD;
    const __nv_bfloat16* Kh = g_kh + (size_t)bh * LSEQ * DHEAD;
    const __nv_bfloat16* Kl = g_kl + (size_t)bh * LSEQ * DHEAD;
    const __nv_bfloat16* Vh = g_vth + (size_t)bh * DHEAD * LSEQ;
    const __nv_bfloat16* Vl = g_vtl + (size_t)bh * DHEAD * LSEQ;

    for (int i = tid; i < 1024; i += 256) {
        const int row = i >> 3, ch = i & 7;
        const uint32_t so = sb + row * QRS + ch * 16;
        cp_async16(so,      Qh + (size_t)(m0 + row) * DHEAD + ch * 8);
        cp_async16(so + QB, Ql + (size_t)(m0 + row) * DHEAD + ch * 8);
    }
    CP_COMMIT();

    const uint32_t st = sb + 2 * QB;       // single KV buffer
    auto load_kv = [&](int kt) {
        const int k0 = kt << 7;
        for (int i = tid; i < 1024; i += 256) {
            const int row = i >> 3, ch = i & 7;
            const uint32_t so = st + row * KRS + ch * 16;
            cp_async16(so,       Kh + (size_t)(k0 + row) * DHEAD + ch * 8);
            cp_async16(so + KBY, Kl + (size_t)(k0 + row) * DHEAD + ch * 8);
        }
        for (int i = tid; i < 1024; i += 256) {
            const int row = i >> 4, ch = i & 15;
            const uint32_t so = st + 2 * KBY + row * VRS + ch * 16;
            cp_async16(so,       Vh + (size_t)row * LSEQ + k0 + ch * 8);
            cp_async16(so + VBY, Vl + (size_t)row * LSEQ + k0 + ch * 8);
        }
    };

    const uint32_t aoff = (uint32_t)((wid * 16 + (lane & 15)) * QRS + (lane >> 4) * 16);
    const uint32_t bKoff = (uint32_t)(((lane >> 4) * 8 + (lane & 7)) * KRS + ((lane >> 3) & 1) * 16);
    const uint32_t bVoff = (uint32_t)(((lane >> 4) * 8 + (lane & 7)) * VRS + ((lane >> 3) & 1) * 16);

    float mrow[2] = {-1e30f, -1e30f};
    float lrow[2] = {0.f, 0.f};
    float Oa[8][4];
#pragma unroll
    for (int i = 0; i < 8; ++i)
#pragma unroll
        for (int j = 0; j < 4; ++j) Oa[i][j] = 0.f;

    for (int kt = 0; kt < nkt; ++kt) {
        load_kv(kt);
        CP_COMMIT();
        CP_WAIT(0);
        __syncthreads();

        float sacc[16][4];
#pragma unroll
        for (int i = 0; i < 16; ++i)
#pragma unroll
            for (int j = 0; j < 4; ++j) sacc[i][j] = 0.f;

#pragma unroll
        for (int ks = 0; ks < 4; ++ks) {
            uint32_t Qf[4], Qg[4];
            ldsm4(sb + aoff + ks * 32,      Qf[0], Qf[1], Qf[2], Qf[3]);
            ldsm4(sb + QB + aoff + ks * 32, Qg[0], Qg[1], Qg[2], Qg[3]);
#pragma unroll
            for (int p = 0; p < 8; ++p) {
                uint32_t bh2[2][2], bl2[2][2];
                ldsm4(st + bKoff + p * 16 * KRS + ks * 32,
                      bh2[0][0], bh2[0][1], bh2[1][0], bh2[1][1]);
                ldsm4(st + KBY + bKoff + p * 16 * KRS + ks * 32,
                      bl2[0][0], bl2[0][1], bl2[1][0], bl2[1][1]);
                mma_bf16(sacc[2*p],   Qf, bh2[0]);
                mma_bf16(sacc[2*p+1], Qf, bh2[1]);
                mma_bf16(sacc[2*p],   Qf, bl2[0]);
                mma_bf16(sacc[2*p+1], Qf, bl2[1]);
                mma_bf16(sacc[2*p],   Qg, bh2[0]);
                mma_bf16(sacc[2*p+1], Qg, bh2[1]);
            }
        }

        if (kt == nkt - 1) {
            const int rl0 = wid * 16 + g;
#pragma unroll
            for (int nt = 0; nt < 16; ++nt) {
                const int c0 = nt * 8 + q * 2;
                if (c0 > rl0)         sacc[nt][0] = -1e30f;
                if (c0 + 1 > rl0)     sacc[nt][1] = -1e30f;
                if (c0 > rl0 + 8)     sacc[nt][2] = -1e30f;
                if (c0 + 1 > rl0 + 8) sacc[nt][3] = -1e30f;
            }
        }

#pragma unroll
        for (int r = 0; r < 2; ++r) {
            float mx = -1e30f;
#pragma unroll
            for (int nt = 0; nt < 16; ++nt)
                mx = fmaxf(mx, fmaxf(sacc[nt][2*r], sacc[nt][2*r+1]));
            mx = fmaxf(mx, __shfl_xor_sync(~0u, mx, 1));
            mx = fmaxf(mx, __shfl_xor_sync(~0u, mx, 2));
            mx *= 0.125f;
            const float mnew = fmaxf(mrow[r], mx);
            const float alpha = __expf(mrow[r] - mnew);
            mrow[r] = mnew;
            float ls = 0.f;
#pragma unroll
            for (int nt = 0; nt < 16; ++nt) {
                float p0 = __expf(fmaf(sacc[nt][2*r], 0.125f, -mnew));
                float p1 = __expf(fmaf(sacc[nt][2*r+1], 0.125f, -mnew));
                sacc[nt][2*r] = p0; sacc[nt][2*r+1] = p1;
                ls += p0 + p1;
            }
            lrow[r] = lrow[r] * alpha + ls;
#pragma unroll
            for (int nt = 0; nt < 8; ++nt) {
                Oa[nt][2*r] *= alpha; Oa[nt][2*r+1] *= alpha;
            }
        }

#pragma unroll
        for (int ks = 0; ks < 8; ++ks) {
            uint32_t Ph[4], Pl[4];
            split_pack(sacc[2*ks][0],   sacc[2*ks][1],   Ph[0], Pl[0]);
            split_pack(sacc[2*ks][2],   sacc[2*ks][3],   Ph[1], Pl[1]);
            split_pack(sacc[2*ks+1][0], sacc[2*ks+1][1], Ph[2], Pl[2]);
            split_pack(sacc[2*ks+1][2], sacc[2*ks+1][3], Ph[3], Pl[3]);
#pragma unroll
            for (int p = 0; p < 4; ++p) {
                uint32_t vh2[2][2], vl2[2][2];
                ldsm4(st + 2 * KBY + bVoff + p * 16 * VRS + ks * 32,
                      vh2[0][0], vh2[0][1], vh2[1][0], vh2[1][1]);
                ldsm4(st + 2 * KBY + VBY + bVoff + p * 16 * VRS + ks * 32,
                      vl2[0][0], vl2[0][1], vl2[1][0], vl2[1][1]);
                mma_bf16(Oa[2*p],   Ph, vh2[0]);
                mma_bf16(Oa[2*p+1], Ph, vh2[1]);
                mma_bf16(Oa[2*p],   Ph, vl2[0]);
                mma_bf16(Oa[2*p+1], Ph, vl2[1]);
                mma_bf16(Oa[2*p],   Pl, vh2[0]);
                mma_bf16(Oa[2*p+1], Pl, vh2[1]);
            }
        }
        __syncthreads();
    }

    const int b = bh >> 4, hh = bh & 15;
#pragma unroll
    for (int r = 0; r < 2; ++r) {
        float l = lrow[r];
        l += __shfl_xor_sync(~0u, l, 1);
        l += __shfl_xor_sync(~0u, l, 2);
        const float inv = 1.0f / l;
        const int row = m0 + wid * 16 + g + r * 8;
#pragma unroll
        for (int nt = 0; nt < 8; ++nt) {
            __half2 hv;
            hv.x = __float2half_rn(Oa[nt][2*r] * inv);
            hv.y = __float2half_rn(Oa[nt][2*r+1] * inv);
            *(__half2*)(g_a + ((size_t)(b * LSEQ + row)) * EMB
                        + hh * DHEAD + nt * 8 + q * 2) = hv;
        }
    }
}

// ---------------------------------------------------------------------------
// Head
// ---------------------------------------------------------------------------
__global__ void head_kernel(const float* __restrict__ x, const float* __restrict__ w_out,
                            const float* __restrict__ b_out, float* __restrict__ out)
{
    __shared__ float red[256];
    const int idx = blockIdx.x, b = idx / KLEN, k = idx % KLEN, tid = threadIdx.x;
    const float* xr = x + ((size_t)(b * LSEQ + 2 * k)) * EMB;
    float acc = 0.f;
#pragma unroll
    for (int c = tid; c < EMB; c += 256) acc = fmaf(xr[c], w_out[c], acc);
    red[tid] = acc;
    __syncthreads();
    for (int off = 128; off > 0; off >>= 1) {
        if (tid < off) red[tid] += red[tid + off];
        __syncthreads();
    }
    if (tid == 0) out[idx] = red[0] + b_out[0];
}

// ---------------------------------------------------------------------------
// Launch
// ---------------------------------------------------------------------------
extern "C" void kernel_launch(void* const* d_in, const int* in_sizes, int n_in,
                              void* d_out, int out_size)
{
    const float* xs     = (const float*)d_in[0];
    const float* ys     = (const float*)d_in[1];
    const float* w_in   = (const float*)d_in[2];
    const float* b_in   = (const float*)d_in[3];
    const float* qkv_w  = (const float*)d_in[4];
    const float* qkv_b  = (const float*)d_in[5];
    const float* proj_w = (const float*)d_in[6];
    const float* proj_b = (const float*)d_in[7];
    const float* ln1_s  = (const float*)d_in[8];
    const float* ln1_b  = (const float*)d_in[9];
    const float* ln2_s  = (const float*)d_in[10];
    const float* ln2_b  = (const float*)d_in[11];
    const float* mlp_w1 = (const float*)d_in[12];
    const float* mlp_b1 = (const float*)d_in[13];
    const float* mlp_w2 = (const float*)d_in[14];
    const float* mlp_b2 = (const float*)d_in[15];
    const float* w_out  = (const float*)d_in[16];
    const float* b_out  = (const float*)d_in[17];
    float* out = (float*)d_out;

    float* x;
    __half *hbuf, *abuf, *fbuf;
    __half *wqh, *wql, *wph, *wpl, *w1h, *w1l, *w2h, *w2l;
    cudaGetSymbolAddress((void**)&x,    g_x);
    cudaGetSymbolAddress((void**)&hbuf, g_h);
    cudaGetSymbolAddress((void**)&abuf, g_a);
    cudaGetSymbolAddress((void**)&fbuf, g_f);
    cudaGetSymbolAddress((void**)&wqh, g_wqh); cudaGetSymbolAddress((void**)&wql, g_wql);
    cudaGetSymbolAddress((void**)&wph, g_wph); cudaGetSymbolAddress((void**)&wpl, g_wpl);
    cudaGetSymbolAddress((void**)&w1h, g_w1h); cudaGetSymbolAddress((void**)&w1l, g_w1l);
    cudaGetSymbolAddress((void**)&w2h, g_w2h); cudaGetSymbolAddress((void**)&w2l, g_w2l);

    cudaFuncSetAttribute(gemm_mma512<1>, cudaFuncAttributeMaxDynamicSharedMemorySize, SMEM_A);
    cudaFuncSetAttribute(gemm_mma256<0>, cudaFuncAttributeMaxDynamicSharedMemorySize, SMEM_B);
    cudaFuncSetAttribute(gemm_mma256<2>, cudaFuncAttributeMaxDynamicSharedMemorySize, SMEM_B);
    cudaFuncSetAttribute(flash_attn,     cudaFuncAttributeMaxDynamicSharedMemorySize, FLASH_SMEM);

    const int M = MROWS;

    transpose_split_all<<<dim3(12288, NLAYER), 256>>>(qkv_w, proj_w, mlp_w1, mlp_w2);
    embed_kernel<<<dim3(EMB / 256, M / 8), 256>>>(xs, ys, w_in, b_in);

    for (int lay = 0; lay < NLAYER; ++lay) {
        const float* qb  = qkv_b  + (size_t)lay * 3 * EMB;
        const float* pb  = proj_b + (size_t)lay * EMB;
        const float* s1  = ln1_s  + (size_t)lay * EMB;
        const float* c1  = ln1_b  + (size_t)lay * EMB;
        const float* s2  = ln2_s  + (size_t)lay * EMB;
        const float* c2  = ln2_b  + (size_t)lay * EMB;
        const float* bb1 = mlp_b1 + (size_t)lay * FFDIM;
        const float* bb2 = mlp_b2 + (size_t)lay * EMB;
        const __half* lwqh = wqh + (size_t)lay * 3 * EMB * EMB;
        const __half* lwql = wql + (size_t)lay * 3 * EMB * EMB;
        const __half* lwph = wph + (size_t)lay * EMB * EMB;
        const __half* lwpl = wpl + (size_t)lay * EMB * EMB;
        const __half* lw1h = w1h + (size_t)lay * FFDIM * EMB;
        const __half* lw1l = w1l + (size_t)lay * FFDIM * EMB;
        const __half* lw2h = w2h + (size_t)lay * EMB * FFDIM;
        const __half* lw2l = w2l + (size_t)lay * EMB * FFDIM;

        ln_kernel<<<M, 256>>>(x, s1, c1, hbuf);
        gemm_mma256<0><<<dim3(3 * EMB / 128, M / 128), 256, SMEM_B>>>(
            hbuf, lwqh, lwql, qb, nullptr, nullptr, nullptr, M, 3 * EMB, EMB);
        flash_attn<<<dim3(NBH, 8), 256, FLASH_SMEM>>>();
        gemm_mma512<1><<<dim3(EMB / 128, M / 128), 512, SMEM_A>>>(
            abuf, lwph, lwpl, pb, x, x, nullptr, M, EMB, EMB);
        ln_kernel<<<M, 256>>>(x, s2, c2, hbuf);
        gemm_mma256<2><<<dim3(FFDIM / 128, M / 128), 256, SMEM_B>>>(
            hbuf, lw1h, lw1l, bb1, nullptr, nullptr, fbuf, M, FFDIM, EMB);
        gemm_mma512<1><<<dim3(EMB / 128, M / 128), 512, SMEM_A>>>(
            fbuf, lw2h, lw2l, bb2, x, x, nullptr, M, EMB, FFDIM);
    }

    head_kernel<<<BATCH * KLEN, 256>>>(x, w_out, b_out, out);
}

// round 15
// speedup vs baseline: 1.0644x; 1.0517x over previous
#include <cuda_runtime.h>
#include <cuda_fp16.h>
#include <cuda_bf16.h>
#include <math.h>
#include <stdint.h>

#define BATCH 2
#define KLEN  512
#define LSEQ  1024
#define EMB   1024
#define NHEAD 16
#define DHEAD 64
#define NLAYER 12
#define FFDIM 4096
#define DIN   64
#define LN_EPS 1e-5f
#define MROWS (BATCH * LSEQ)   // 2048
#define NBH   (BATCH * NHEAD)  // 32

// ---------------------------------------------------------------------------
// Scratch (device globals; zero-initialized; allocation forbidden)
// ---------------------------------------------------------------------------
__device__ float g_x [MROWS * EMB];
__device__ __half g_h[MROWS * EMB];
__device__ __half g_a[MROWS * EMB];
__device__ __half g_f[MROWS * FFDIM];
__device__ __nv_bfloat16 g_qh[NBH * LSEQ * DHEAD];
__device__ __nv_bfloat16 g_ql[NBH * LSEQ * DHEAD];
__device__ __nv_bfloat16 g_kh[NBH * LSEQ * DHEAD];
__device__ __nv_bfloat16 g_kl[NBH * LSEQ * DHEAD];
__device__ __nv_bfloat16 g_vth[NBH * DHEAD * LSEQ];
__device__ __nv_bfloat16 g_vtl[NBH * DHEAD * LSEQ];
__device__ __half g_wqh[NLAYER * 3 * EMB * EMB];
__device__ __half g_wql[NLAYER * 3 * EMB * EMB];
__device__ __half g_wph[NLAYER * EMB * EMB];
__device__ __half g_wpl[NLAYER * EMB * EMB];
__device__ __half g_w1h[NLAYER * FFDIM * EMB];
__device__ __half g_w1l[NLAYER * FFDIM * EMB];
__device__ __half g_w2h[NLAYER * EMB * FFDIM];
__device__ __half g_w2l[NLAYER * EMB * FFDIM];

// ---------------------------------------------------------------------------
// Helpers
// ---------------------------------------------------------------------------
__device__ __forceinline__ uint32_t smem_u32(const void* p) {
    uint32_t a;
    asm("{ .reg .u64 t; cvta.to.shared.u64 t, %1; cvt.u32.u64 %0, t; }" : "=r"(a) : "l"(p));
    return a;
}
__device__ __forceinline__ void cp_async16(uint32_t s, const void* g) {
    asm volatile("cp.async.cg.shared.global [%0], [%1], 16;" :: "r"(s), "l"(g));
}
#define CP_COMMIT() asm volatile("cp.async.commit_group;" ::: "memory")
#define CP_WAIT(n)  asm volatile("cp.async.wait_group %0;" :: "n"(n) : "memory")

__device__ __forceinline__ void ldsm4(uint32_t a, uint32_t& r0, uint32_t& r1,
                                      uint32_t& r2, uint32_t& r3) {
    asm volatile("ldmatrix.sync.aligned.m8n8.x4.shared.b16 {%0,%1,%2,%3}, [%4];"
                 : "=r"(r0), "=r"(r1), "=r"(r2), "=r"(r3) : "r"(a));
}
__device__ __forceinline__ void mma_f16(float* d, const uint32_t* a, const uint32_t* b) {
    asm volatile(
        "mma.sync.aligned.m16n8k16.row.col.f32.f16.f16.f32 "
        "{%0,%1,%2,%3}, {%4,%5,%6,%7}, {%8,%9}, {%0,%1,%2,%3};"
        : "+f"(d[0]), "+f"(d[1]), "+f"(d[2]), "+f"(d[3])
        : "r"(a[0]), "r"(a[1]), "r"(a[2]), "r"(a[3]), "r"(b[0]), "r"(b[1]));
}
__device__ __forceinline__ void mma_bf16(float* d, const uint32_t* a, const uint32_t* b) {
    asm volatile(
        "mma.sync.aligned.m16n8k16.row.col.f32.bf16.bf16.f32 "
        "{%0,%1,%2,%3}, {%4,%5,%6,%7}, {%8,%9}, {%0,%1,%2,%3};"
        : "+f"(d[0]), "+f"(d[1]), "+f"(d[2]), "+f"(d[3])
        : "r"(a[0]), "r"(a[1]), "r"(a[2]), "r"(a[3]), "r"(b[0]), "r"(b[1]));
}
__device__ __forceinline__ void split_f16(float v, __half& hi, __half& lo) {
    hi = __float2half_rn(v);
    lo = __float2half_rn(v - __half2float(hi));
}
__device__ __forceinline__ void split_bf(float v, __nv_bfloat16& hi, __nv_bfloat16& lo) {
    hi = __float2bfloat16(v);
    lo = __float2bfloat16(v - __bfloat162float(hi));
}
__device__ __forceinline__ void split_pack(float v0, float v1, uint32_t& ph, uint32_t& pl) {
    asm("cvt.rn.bf16x2.f32 %0, %1, %2;" : "=r"(ph) : "f"(v1), "f"(v0));
    float h0 = __uint_as_float(ph << 16);
    float h1 = __uint_as_float(ph & 0xFFFF0000u);
    float r0 = v0 - h0, r1 = v1 - h1;
    asm("cvt.rn.bf16x2.f32 %0, %1, %2;" : "=r"(pl) : "f"(r1), "f"(r0));
}

// ---------------------------------------------------------------------------
// Epilogue (shared)
// EPI: 0 = write qkv splits   1 = residual + fp32 out   2 = GELU + fp16 out
// ---------------------------------------------------------------------------
template <int EPI>
__device__ __forceinline__ void gemm_epilogue_elem(
    int row, int col, float v0, float v1, int N,
    const float* __restrict__ Rres, float* __restrict__ C, __half* __restrict__ Ch)
{
    if (EPI == 0) {
        const int b = row >> 10, l = row & 1023;
        const int part = col >> 10;
        const int h = (col & 1023) >> 6, d = col & 63;
        const int bh = b * NHEAD + h;
        __nv_bfloat16 h0, l0, h1, l1;
        split_bf(v0, h0, l0); split_bf(v1, h1, l1);
        if (part == 2) {
            const size_t o = ((size_t)bh * DHEAD + d) * LSEQ + l;
            g_vth[o] = h0; g_vtl[o] = l0;
            g_vth[o + LSEQ] = h1; g_vtl[o + LSEQ] = l1;
        } else {
            const size_t o = ((size_t)bh * LSEQ + l) * DHEAD + d;
            __nv_bfloat162 hv; hv.x = h0; hv.y = h1;
            __nv_bfloat162 lv; lv.x = l0; lv.y = l1;
            if (part == 0) {
                *(__nv_bfloat162*)(g_qh + o) = hv;
                *(__nv_bfloat162*)(g_ql + o) = lv;
            } else {
                *(__nv_bfloat162*)(g_kh + o) = hv;
                *(__nv_bfloat162*)(g_kl + o) = lv;
            }
        }
    } else {
        const size_t o = (size_t)row * N + col;
        if (EPI == 1) {
            v0 += Rres[o]; v1 += Rres[o + 1];
            float2 fv = {v0, v1}; *(float2*)(C + o) = fv;
        } else {
            v0 = 0.5f * v0 * (1.0f + erff(v0 * 0.70710678118654752f));
            v1 = 0.5f * v1 * (1.0f + erff(v1 * 0.70710678118654752f));
            __half2 hv; hv.x = __float2half_rn(v0); hv.y = __float2half_rn(v1);
            *(__half2*)(Ch + o) = hv;
        }
    }
}

// ---------------------------------------------------------------------------
// Variant A: 128x128 tile, 512 threads, 16 warps 4x4, warp 32x32, 4-stage.
// SMALL grids (proj, mlp2: 128 CTAs).
// ---------------------------------------------------------------------------
#define RSTRIDE 80
#define MAT_BYTES (128 * RSTRIDE)
#define STG_A (3 * MAT_BYTES)
#define NSTG_A 4
#define SMEM_A (NSTG_A * STG_A)            // 122880

template <int EPI>
__global__ void __launch_bounds__(512, 1) gemm_mma512(
    const __half* __restrict__ A,
    const __half* __restrict__ Bh, const __half* __restrict__ Bl,
    const float* __restrict__ bias, const float* __restrict__ Rres,
    float* __restrict__ C, __half* __restrict__ Ch,
    int M, int N, int K)
{
    extern __shared__ char smem[];
    const uint32_t sbase = smem_u32(smem);
    const int tid = threadIdx.x, wid = tid >> 5, lane = tid & 31;
    const int m0 = blockIdx.y * 128, n0 = blockIdx.x * 128;
    const int wm = wid & 3, wn = wid >> 2;
    const int g = lane >> 2, q = lane & 3;
    const int lrow = tid >> 2, lch = tid & 3;
    const uint32_t soff = (uint32_t)(lrow * RSTRIDE + lch * 16);
    const uint32_t aoff = (uint32_t)((wm * 32 + (lane & 15)) * RSTRIDE + (lane >> 4) * 16);
    const uint32_t boff = (uint32_t)((wn * 32 + (lane >> 4) * 8 + (lane & 7)) * RSTRIDE
                                     + ((lane >> 3) & 1) * 16);

    float acc[2][4][4];
#pragma unroll
    for (int i = 0; i < 2; ++i)
#pragma unroll
        for (int j = 0; j < 4; ++j)
#pragma unroll
            for (int r = 0; r < 4; ++r) acc[i][j][r] = 0.f;

    const int CH = K >> 5;
    auto load_stage = [&](int c) {
        const int k0 = c << 5;
        const uint32_t sb = sbase + (c & (NSTG_A - 1)) * STG_A + soff;
        const size_t ga = (size_t)(m0 + lrow) * K + k0 + lch * 8;
        const size_t gb = (size_t)(n0 + lrow) * K + k0 + lch * 8;
        cp_async16(sb,                 A  + ga);
        cp_async16(sb + MAT_BYTES,     Bh + gb);
        cp_async16(sb + 2 * MAT_BYTES, Bl + gb);
    };
    load_stage(0); CP_COMMIT();
    load_stage(1); CP_COMMIT();
    load_stage(2); CP_COMMIT();

    for (int c = 0; c < CH; ++c) {
        CP_WAIT(2);
        __syncthreads();
        const uint32_t sA = sbase + (c & (NSTG_A - 1)) * STG_A;
        const uint32_t sB = sA + MAT_BYTES;
#pragma unroll
        for (int ks = 0; ks < 2; ++ks) {
            uint32_t Af[2][4], Bhf[4][2], Blf[4][2];
#pragma unroll
            for (int mt = 0; mt < 2; ++mt) {
                const uint32_t aa = sA + aoff + mt * 16 * RSTRIDE + ks * 32;
                ldsm4(aa, Af[mt][0], Af[mt][1], Af[mt][2], Af[mt][3]);
            }
#pragma unroll
            for (int p = 0; p < 2; ++p) {
                const uint32_t ba = sB + boff + p * 16 * RSTRIDE + ks * 32;
                ldsm4(ba,             Bhf[2*p][0], Bhf[2*p][1], Bhf[2*p+1][0], Bhf[2*p+1][1]);
                ldsm4(ba + MAT_BYTES, Blf[2*p][0], Blf[2*p][1], Blf[2*p+1][0], Blf[2*p+1][1]);
            }
#pragma unroll
            for (int mt = 0; mt < 2; ++mt)
#pragma unroll
                for (int nt = 0; nt < 4; ++nt)
                    mma_f16(acc[mt][nt], Af[mt], Bhf[nt]);
#pragma unroll
            for (int mt = 0; mt < 2; ++mt)
#pragma unroll
                for (int nt = 0; nt < 4; ++nt)
                    mma_f16(acc[mt][nt], Af[mt], Blf[nt]);
        }
        if (c + 3 < CH) load_stage(c + 3);
        CP_COMMIT();
    }

#pragma unroll
    for (int nt = 0; nt < 4; ++nt) {
        const int col = n0 + wn * 32 + nt * 8 + q * 2;
        const float bia0 = bias[col], bia1 = bias[col + 1];
#pragma unroll
        for (int mt = 0; mt < 2; ++mt)
#pragma unroll
            for (int h2 = 0; h2 < 2; ++h2) {
                const int row = m0 + wm * 32 + mt * 16 + g + h2 * 8;
                gemm_epilogue_elem<EPI>(row, col,
                    acc[mt][nt][h2 * 2 + 0] + bia0,
                    acc[mt][nt][h2 * 2 + 1] + bia1, N, Rres, C, Ch);
            }
    }
}

// ---------------------------------------------------------------------------
// Variant B: 256 threads, 8 warps 2x4, warp tile 64x32, 3-stage, 2 CTA/SM.
// LARGE grids (qkv: 384 CTAs, mlp1: 512 CTAs).
// ---------------------------------------------------------------------------
#define STG_B (3 * MAT_BYTES)              // 30720
#define NSTG_B 3
#define SMEM_B (NSTG_B * STG_B)            // 92160

template <int EPI>
__global__ void __launch_bounds__(256, 2) gemm_mma256(
    const __half* __restrict__ A,
    const __half* __restrict__ Bh, const __half* __restrict__ Bl,
    const float* __restrict__ bias, const float* __restrict__ Rres,
    float* __restrict__ C, __half* __restrict__ Ch,
    int M, int N, int K)
{
    extern __shared__ char smem[];
    const uint32_t sbase = smem_u32(smem);
    const int tid = threadIdx.x, wid = tid >> 5, lane = tid & 31;
    const int m0 = blockIdx.y * 128, n0 = blockIdx.x * 128;
    const int wm = wid & 1, wn = wid >> 1;
    const int g = lane >> 2, q = lane & 3;
    const uint32_t aoff = (uint32_t)((wm * 64 + (lane & 15)) * RSTRIDE + (lane >> 4) * 16);
    const uint32_t boff = (uint32_t)((wn * 32 + (lane >> 4) * 8 + (lane & 7)) * RSTRIDE
                                     + ((lane >> 3) & 1) * 16);

    float acc[4][4][4];
#pragma unroll
    for (int i = 0; i < 4; ++i)
#pragma unroll
        for (int j = 0; j < 4; ++j)
#pragma unroll
            for (int r = 0; r < 4; ++r) acc[i][j][r] = 0.f;

    const int CH = K >> 5;
    auto load_stage = [&](int c, int buf) {
        const int k0 = c << 5;
        const uint32_t sbuf = sbase + buf * STG_B;
#pragma unroll
        for (int u = 0; u < 2; ++u) {
            const int i = tid + (u << 8);
            const int row = i >> 2, ch = i & 3;
            const uint32_t so = sbuf + row * RSTRIDE + ch * 16;
            const size_t ga = (size_t)(m0 + row) * K + k0 + ch * 8;
            const size_t gb = (size_t)(n0 + row) * K + k0 + ch * 8;
            cp_async16(so,                 A  + ga);
            cp_async16(so + MAT_BYTES,     Bh + gb);
            cp_async16(so + 2 * MAT_BYTES, Bl + gb);
        }
    };
    load_stage(0, 0); CP_COMMIT();
    load_stage(1, 1); CP_COMMIT();

    int cb = 0, lb = 2;
    for (int c = 0; c < CH; ++c) {
        CP_WAIT(1);
        __syncthreads();
        const uint32_t sA = sbase + cb * STG_B;
        const uint32_t sB = sA + MAT_BYTES;
#pragma unroll
        for (int ks = 0; ks < 2; ++ks) {
            uint32_t Af[4][4], Bhf[4][2], Blf[4][2];
#pragma unroll
            for (int mt = 0; mt < 4; ++mt) {
                const uint32_t aa = sA + aoff + mt * 16 * RSTRIDE + ks * 32;
                ldsm4(aa, Af[mt][0], Af[mt][1], Af[mt][2], Af[mt][3]);
            }
#pragma unroll
            for (int p = 0; p < 2; ++p) {
                const uint32_t ba = sB + boff + p * 16 * RSTRIDE + ks * 32;
                ldsm4(ba,             Bhf[2*p][0], Bhf[2*p][1], Bhf[2*p+1][0], Bhf[2*p+1][1]);
                ldsm4(ba + MAT_BYTES, Blf[2*p][0], Blf[2*p][1], Blf[2*p+1][0], Blf[2*p+1][1]);
            }
#pragma unroll
            for (int mt = 0; mt < 4; ++mt)
#pragma unroll
                for (int nt = 0; nt < 4; ++nt)
                    mma_f16(acc[mt][nt], Af[mt], Bhf[nt]);
#pragma unroll
            for (int mt = 0; mt < 4; ++mt)
#pragma unroll
                for (int nt = 0; nt < 4; ++nt)
                    mma_f16(acc[mt][nt], Af[mt], Blf[nt]);
        }
        if (c + 2 < CH) load_stage(c + 2, lb);
        CP_COMMIT();
        cb = (cb + 1 == NSTG_B) ? 0 : cb + 1;
        lb = (lb + 1 == NSTG_B) ? 0 : lb + 1;
    }

#pragma unroll
    for (int nt = 0; nt < 4; ++nt) {
        const int col = n0 + wn * 32 + nt * 8 + q * 2;
        const float bia0 = bias[col], bia1 = bias[col + 1];
#pragma unroll
        for (int mt = 0; mt < 4; ++mt)
#pragma unroll
            for (int h2 = 0; h2 < 2; ++h2) {
                const int row = m0 + wm * 64 + mt * 16 + g + h2 * 8;
                gemm_epilogue_elem<EPI>(row, col,
                    acc[mt][nt][h2 * 2 + 0] + bia0,
                    acc[mt][nt][h2 * 2 + 1] + bia1, N, Rres, C, Ch);
            }
    }
}

// ---------------------------------------------------------------------------
// Fused weight transpose + split — vectorized
// ---------------------------------------------------------------------------
__global__ void __launch_bounds__(256) transpose_split_all(
    const float* __restrict__ qkv_w, const float* __restrict__ proj_w,
    const float* __restrict__ mlp_w1, const float* __restrict__ mlp_w2)
{
    __shared__ float t[32][33];
    const int lay = blockIdx.y;
    int tt = blockIdx.x;
    const float* W; __half *Th, *Tl; int K, N;
    if (tt < 3072)      { W = qkv_w;  Th = g_wqh; Tl = g_wql; K = EMB;   N = 3 * EMB; }
    else if (tt < 4096) { W = proj_w; Th = g_wph; Tl = g_wpl; K = EMB;   N = EMB;   tt -= 3072; }
    else if (tt < 8192) { W = mlp_w1; Th = g_w1h; Tl = g_w1l; K = EMB;   N = FFDIM; tt -= 4096; }
    else                { W = mlp_w2; Th = g_w2h; Tl = g_w2l; K = FFDIM; N = EMB;   tt -= 8192; }
    const int ntx = N >> 5;
    const int n0 = (tt % ntx) * 32, k0 = (tt / ntx) * 32;
    const float* Ws = W + (size_t)lay * K * N;
    __half* Ths = Th + (size_t)lay * K * N;
    __half* Tls = Tl + (size_t)lay * K * N;
    const int tid = threadIdx.x;

#pragma unroll
    for (int u = 0; u < 4; ++u) {
        const int i = tid + u * 256;
        const int row = i >> 5, col = i & 31;
        t[row][col] = Ws[(size_t)(k0 + row) * N + n0 + col];
    }
    __syncthreads();

#pragma unroll
    for (int u = 0; u < 2; ++u) {
        const int i = tid + u * 256;
        const int ni = i >> 4, kh = i & 15;
        const float v0 = t[2 * kh][ni];
        const float v1 = t[2 * kh + 1][ni];
        __half h0, l0, h1, l1;
        split_f16(v0, h0, l0); split_f16(v1, h1, l1);
        __half2 hv; hv.x = h0; hv.y = h1;
        __half2 lv; lv.x = l0; lv.y = l1;
        const size_t o = (size_t)(n0 + ni) * K + k0 + 2 * kh;
        *(__half2*)(Ths + o) = hv;
        *(__half2*)(Tls + o) = lv;
    }
}

// ---------------------------------------------------------------------------
// Embed: 8 rows per block
// ---------------------------------------------------------------------------
__global__ void __launch_bounds__(256) embed_kernel(
    const float* __restrict__ xs, const float* __restrict__ ys,
    const float* __restrict__ w_in, const float* __restrict__ b_in)
{
    __shared__ float z[8][DIN];
    const int base = blockIdx.y * 8;
    const int tid = threadIdx.x;
#pragma unroll
    for (int u = 0; u < 2; ++u) {
        const int i = tid + u * 256;
        const int r = i >> 6, d = i & 63;
        const int row = base + r;
        const int b = row / LSEQ, l = row % LSEQ, k = l >> 1;
        float v;
        if ((l & 1) == 0) v = xs[(b * KLEN + k) * DIN + d];
        else              v = (d == 0) ? ys[b * KLEN + k] : 0.0f;
        z[r][d] = v;
    }
    __syncthreads();
    const int n = blockIdx.x * 256 + tid;
    float acc[8];
    const float bi = b_in[n];
#pragma unroll
    for (int r = 0; r < 8; ++r) acc[r] = bi;
#pragma unroll
    for (int d = 0; d < DIN; ++d) {
        const float w = w_in[d * EMB + n];
#pragma unroll
        for (int r = 0; r < 8; ++r) acc[r] = fmaf(z[r][d], w, acc[r]);
    }
#pragma unroll
    for (int r = 0; r < 8; ++r)
        g_x[(size_t)(base + r) * EMB + n] = acc[r];
}

// ---------------------------------------------------------------------------
// LayerNorm -> fp16 (single pass)
// ---------------------------------------------------------------------------
__global__ void __launch_bounds__(256) ln_kernel(
    const float* __restrict__ x,
    const float* __restrict__ s, const float* __restrict__ bb,
    __half* __restrict__ oh)
{
    __shared__ float red1[8], red2[8], stats[2];
    const int row = blockIdx.x, tid = threadIdx.x;
    const int wid = tid >> 5, lane = tid & 31;
    const float4 v = *(const float4*)(x + (size_t)row * EMB + tid * 4);
    float sum = v.x + v.y + v.z + v.w;
    float sq  = v.x * v.x + v.y * v.y + v.z * v.z + v.w * v.w;
#pragma unroll
    for (int o = 16; o; o >>= 1) {
        sum += __shfl_xor_sync(~0u, sum, o);
        sq  += __shfl_xor_sync(~0u, sq, o);
    }
    if (lane == 0) { red1[wid] = sum; red2[wid] = sq; }
    __syncthreads();
    if (tid == 0) {
        float ts = 0.f, tq = 0.f;
#pragma unroll
        for (int i = 0; i < 8; ++i) { ts += red1[i]; tq += red2[i]; }
        const float m = ts * (1.0f / EMB);
        const float var = tq * (1.0f / EMB) - m * m;
        stats[0] = m; stats[1] = rsqrtf(var + LN_EPS);
    }
    __syncthreads();
    const float m = stats[0], rstd = stats[1];
    const float4 sv = *(const float4*)(s + tid * 4);
    const float4 bv = *(const float4*)(bb + tid * 4);
    const float o0 = (v.x - m) * rstd * sv.x + bv.x;
    const float o1 = (v.y - m) * rstd * sv.y + bv.y;
    const float o2 = (v.z - m) * rstd * sv.z + bv.z;
    const float o3 = (v.w - m) * rstd * sv.w + bv.w;
    __half2 h01; h01.x = __float2half_rn(o0); h01.y = __float2half_rn(o1);
    __half2 h23; h23.x = __float2half_rn(o2); h23.y = __float2half_rn(o3);
    uint2 pk;
    pk.x = *(uint32_t*)&h01; pk.y = *(uint32_t*)&h23;
    *(uint2*)(oh + (size_t)row * EMB + tid * 4) = pk;
}

// ---------------------------------------------------------------------------
// Flash attention (R11 verified): double-buffered KV, one CTA per
// (bh, 128-query block), 256 threads = 8 warps.
// ---------------------------------------------------------------------------
#define QRS 144
#define KRS 144
#define VRS 272
#define QB (128 * QRS)
#define KBY (128 * KRS)
#define VBY (64 * VRS)
#define KVSTAGE (2 * KBY + 2 * VBY)
#define FLASH_SMEM (2 * QB + 2 * KVSTAGE)  // 180224

__global__ void __launch_bounds__(256, 1) flash_attn()
{
    extern __shared__ char smem[];
    const uint32_t sb = smem_u32(smem);
    const int tid = threadIdx.x, wid = tid >> 5, lane = tid & 31;
    const int g = lane >> 2, q = lane & 3;
    const int bh = blockIdx.x;
    const int m0 = (7 - (int)blockIdx.y) * 128;
    const int nkt = (m0 >> 7) + 1;

    const __nv_bfloat16* Qh = g_qh + (size_t)bh * LSEQ * DHEAD;
    const __nv_bfloat16* Ql = g_ql + (size_t)bh * LSEQ * DHEAD;
    const __nv_bfloat16* Kh = g_kh + (size_t)bh * LSEQ * DHEAD;
    const __nv_bfloat16* Kl = g_kl + (size_t)bh * LSEQ * DHEAD;
    const __nv_bfloat16* Vh = g_vth + (size_t)bh * DHEAD * LSEQ;
    const __nv_bfloat16* Vl = g_vtl + (size_t)bh * DHEAD * LSEQ;

    for (int i = tid; i < 1024; i += 256) {
        const int row = i >> 3, ch = i & 7;
        const uint32_t so = sb + row * QRS + ch * 16;
        cp_async16(so,      Qh + (size_t)(m0 + row) * DHEAD + ch * 8);
        cp_async16(so + QB, Ql + (size_t)(m0 + row) * DHEAD + ch * 8);
    }
    auto load_kv = [&](int kt) {
        const int k0 = kt << 7;
        const uint32_t st = sb + 2 * QB + (kt & 1) * KVSTAGE;
        for (int i = tid; i < 1024; i += 256) {
            const int row = i >> 3, ch = i & 7;
            const uint32_t so = st + row * KRS + ch * 16;
            cp_async16(so,       Kh + (size_t)(k0 + row) * DHEAD + ch * 8);
            cp_async16(so + KBY, Kl + (size_t)(k0 + row) * DHEAD + ch * 8);
        }
        for (int i = tid; i < 1024; i += 256) {
            const int row = i >> 4, ch = i & 15;
            const uint32_t so = st + 2 * KBY + row * VRS + ch * 16;
            cp_async16(so,       Vh + (size_t)row * LSEQ + k0 + ch * 8);
            cp_async16(so + VBY, Vl + (size_t)row * LSEQ + k0 + ch * 8);
        }
    };
    load_kv(0);
    CP_COMMIT();

    const uint32_t aoff = (uint32_t)((wid * 16 + (lane & 15)) * QRS + (lane >> 4) * 16);
    const uint32_t bKoff = (uint32_t)(((lane >> 4) * 8 + (lane & 7)) * KRS + ((lane >> 3) & 1) * 16);
    const uint32_t bVoff = (uint32_t)(((lane >> 4) * 8 + (lane & 7)) * VRS + ((lane >> 3) & 1) * 16);

    float mrow[2] = {-1e30f, -1e30f};
    float lrow[2] = {0.f, 0.f};
    float Oa[8][4];
#pragma unroll
    for (int i = 0; i < 8; ++i)
#pragma unroll
        for (int j = 0; j < 4; ++j) Oa[i][j] = 0.f;

    for (int kt = 0; kt < nkt; ++kt) {
        if (kt + 1 < nkt) load_kv(kt + 1);
        CP_COMMIT();
        CP_WAIT(1);
        __syncthreads();

        const uint32_t st = sb + 2 * QB + (kt & 1) * KVSTAGE;
        float sacc[16][4];
#pragma unroll
        for (int i = 0; i < 16; ++i)
#pragma unroll
            for (int j = 0; j < 4; ++j) sacc[i][j] = 0.f;

#pragma unroll
        for (int ks = 0; ks < 4; ++ks) {
            uint32_t Qf[4], Qg[4];
            ldsm4(sb + aoff + ks * 32,      Qf[0], Qf[1], Qf[2], Qf[3]);
            ldsm4(sb + QB + aoff + ks * 32, Qg[0], Qg[1], Qg[2], Qg[3]);
#pragma unroll
            for (int p = 0; p < 8; ++p) {
                uint32_t bh2[2][2], bl2[2][2];
                ldsm4(st + bKoff + p * 16 * KRS + ks * 32,
                      bh2[0][0], bh2[0][1], bh2[1][0], bh2[1][1]);
                ldsm4(st + KBY + bKoff + p * 16 * KRS + ks * 32,
                      bl2[0][0], bl2[0][1], bl2[1][0], bl2[1][1]);
                mma_bf16(sacc[2*p],   Qf, bh2[0]);
                mma_bf16(sacc[2*p+1], Qf, bh2[1]);
                mma_bf16(sacc[2*p],   Qf, bl2[0]);
                mma_bf16(sacc[2*p+1], Qf, bl2[1]);
                mma_bf16(sacc[2*p],   Qg, bh2[0]);
                mma_bf16(sacc[2*p+1], Qg, bh2[1]);
            }
        }

        if (kt == nkt - 1) {
            const int rl0 = wid * 16 + g;
#pragma unroll
            for (int nt = 0; nt < 16; ++nt) {
                const int c0 = nt * 8 + q * 2;
                if (c0 > rl0)         sacc[nt][0] = -1e30f;
                if (c0 + 1 > rl0)     sacc[nt][1] = -1e30f;
                if (c0 > rl0 + 8)     sacc[nt][2] = -1e30f;
                if (c0 + 1 > rl0 + 8) sacc[nt][3] = -1e30f;
            }
        }

#pragma unroll
        for (int r = 0; r < 2; ++r) {
            float mx = -1e30f;
#pragma unroll
            for (int nt = 0; nt < 16; ++nt)
                mx = fmaxf(mx, fmaxf(sacc[nt][2*r], sacc[nt][2*r+1]));
            mx = fmaxf(mx, __shfl_xor_sync(~0u, mx, 1));
            mx = fmaxf(mx, __shfl_xor_sync(~0u, mx, 2));
            mx *= 0.125f;
            const float mnew = fmaxf(mrow[r], mx);
            const float alpha = __expf(mrow[r] - mnew);
            mrow[r] = mnew;
            float ls = 0.f;
#pragma unroll
            for (int nt = 0; nt < 16; ++nt) {
                float p0 = __expf(fmaf(sacc[nt][2*r], 0.125f, -mnew));
                float p1 = __expf(fmaf(sacc[nt][2*r+1], 0.125f, -mnew));
                sacc[nt][2*r] = p0; sacc[nt][2*r+1] = p1;
                ls += p0 + p1;
            }
            lrow[r] = lrow[r] * alpha + ls;
#pragma unroll
            for (int nt = 0; nt < 8; ++nt) {
                Oa[nt][2*r] *= alpha; Oa[nt][2*r+1] *= alpha;
            }
        }

#pragma unroll
        for (int ks = 0; ks < 8; ++ks) {
            uint32_t Ph[4], Pl[4];
            split_pack(sacc[2*ks][0],   sacc[2*ks][1],   Ph[0], Pl[0]);
            split_pack(sacc[2*ks][2],   sacc[2*ks][3],   Ph[1], Pl[1]);
            split_pack(sacc[2*ks+1][0], sacc[2*ks+1][1], Ph[2], Pl[2]);
            split_pack(sacc[2*ks+1][2], sacc[2*ks+1][3], Ph[3], Pl[3]);
#pragma unroll
            for (int p = 0; p < 4; ++p) {
                uint32_t vh2[2][2], vl2[2][2];
                ldsm4(st + 2 * KBY + bVoff + p * 16 * VRS + ks * 32,
                      vh2[0][0], vh2[0][1], vh2[1][0], vh2[1][1]);
                ldsm4(st + 2 * KBY + VBY + bVoff + p * 16 * VRS + ks * 32,
                      vl2[0][0], vl2[0][1], vl2[1][0], vl2[1][1]);
                mma_bf16(Oa[2*p],   Ph, vh2[0]);
                mma_bf16(Oa[2*p+1], Ph, vh2[1]);
                mma_bf16(Oa[2*p],   Ph, vl2[0]);
                mma_bf16(Oa[2*p+1], Ph, vl2[1]);
                mma_bf16(Oa[2*p],   Pl, vh2[0]);
                mma_bf16(Oa[2*p+1], Pl, vh2[1]);
            }
        }
        __syncthreads();
    }

    const int b = bh >> 4, hh = bh & 15;
#pragma unroll
    for (int r = 0; r < 2; ++r) {
        float l = lrow[r];
        l += __shfl_xor_sync(~0u, l, 1);
        l += __shfl_xor_sync(~0u, l, 2);
        const float inv = 1.0f / l;
        const int row = m0 + wid * 16 + g + r * 8;
#pragma unroll
        for (int nt = 0; nt < 8; ++nt) {
            __half2 hv;
            hv.x = __float2half_rn(Oa[nt][2*r] * inv);
            hv.y = __float2half_rn(Oa[nt][2*r+1] * inv);
            *(__half2*)(g_a + ((size_t)(b * LSEQ + row)) * EMB
                        + hh * DHEAD + nt * 8 + q * 2) = hv;
        }
    }
}

// ---------------------------------------------------------------------------
// Head
// ---------------------------------------------------------------------------
__global__ void head_kernel(const float* __restrict__ x, const float* __restrict__ w_out,
                            const float* __restrict__ b_out, float* __restrict__ out)
{
    __shared__ float red[256];
    const int idx = blockIdx.x, b = idx / KLEN, k = idx % KLEN, tid = threadIdx.x;
    const float* xr = x + ((size_t)(b * LSEQ + 2 * k)) * EMB;
    float acc = 0.f;
#pragma unroll
    for (int c = tid; c < EMB; c += 256) acc = fmaf(xr[c], w_out[c], acc);
    red[tid] = acc;
    __syncthreads();
    for (int off = 128; off > 0; off >>= 1) {
        if (tid < off) red[tid] += red[tid + off];
        __syncthreads();
    }
    if (tid == 0) out[idx] = red[0] + b_out[0];
}

// ---------------------------------------------------------------------------
// Launch
// ---------------------------------------------------------------------------
extern "C" void kernel_launch(void* const* d_in, const int* in_sizes, int n_in,
                              void* d_out, int out_size)
{
    const float* xs     = (const float*)d_in[0];
    const float* ys     = (const float*)d_in[1];
    const float* w_in   = (const float*)d_in[2];
    const float* b_in   = (const float*)d_in[3];
    const float* qkv_w  = (const float*)d_in[4];
    const float* qkv_b  = (const float*)d_in[5];
    const float* proj_w = (const float*)d_in[6];
    const float* proj_b = (const float*)d_in[7];
    const float* ln1_s  = (const float*)d_in[8];
    const float* ln1_b  = (const float*)d_in[9];
    const float* ln2_s  = (const float*)d_in[10];
    const float* ln2_b  = (const float*)d_in[11];
    const float* mlp_w1 = (const float*)d_in[12];
    const float* mlp_b1 = (const float*)d_in[13];
    const float* mlp_w2 = (const float*)d_in[14];
    const float* mlp_b2 = (const float*)d_in[15];
    const float* w_out  = (const float*)d_in[16];
    const float* b_out  = (const float*)d_in[17];
    float* out = (float*)d_out;

    float* x;
    __half *hbuf, *abuf, *fbuf;
    __half *wqh, *wql, *wph, *wpl, *w1h, *w1l, *w2h, *w2l;
    cudaGetSymbolAddress((void**)&x,    g_x);
    cudaGetSymbolAddress((void**)&hbuf, g_h);
    cudaGetSymbolAddress((void**)&abuf, g_a);
    cudaGetSymbolAddress((void**)&fbuf, g_f);
    cudaGetSymbolAddress((void**)&wqh, g_wqh); cudaGetSymbolAddress((void**)&wql, g_wql);
    cudaGetSymbolAddress((void**)&wph, g_wph); cudaGetSymbolAddress((void**)&wpl, g_wpl);
    cudaGetSymbolAddress((void**)&w1h, g_w1h); cudaGetSymbolAddress((void**)&w1l, g_w1l);
    cudaGetSymbolAddress((void**)&w2h, g_w2h); cudaGetSymbolAddress((void**)&w2l, g_w2l);

    cudaFuncSetAttribute(gemm_mma512<1>, cudaFuncAttributeMaxDynamicSharedMemorySize, SMEM_A);
    cudaFuncSetAttribute(gemm_mma256<0>, cudaFuncAttributeMaxDynamicSharedMemorySize, SMEM_B);
    cudaFuncSetAttribute(gemm_mma256<2>, cudaFuncAttributeMaxDynamicSharedMemorySize, SMEM_B);
    cudaFuncSetAttribute(flash_attn,     cudaFuncAttributeMaxDynamicSharedMemorySize, FLASH_SMEM);

    const int M = MROWS;

    transpose_split_all<<<dim3(12288, NLAYER), 256>>>(qkv_w, proj_w, mlp_w1, mlp_w2);
    embed_kernel<<<dim3(EMB / 256, M / 8), 256>>>(xs, ys, w_in, b_in);

    for (int lay = 0; lay < NLAYER; ++lay) {
        const float* qb  = qkv_b  + (size_t)lay * 3 * EMB;
        const float* pb  = proj_b + (size_t)lay * EMB;
        const float* s1  = ln1_s  + (size_t)lay * EMB;
        const float* c1  = ln1_b  + (size_t)lay * EMB;
        const float* s2  = ln2_s  + (size_t)lay * EMB;
        const float* c2  = ln2_b  + (size_t)lay * EMB;
        const float* bb1 = mlp_b1 + (size_t)lay * FFDIM;
        const float* bb2 = mlp_b2 + (size_t)lay * EMB;
        const __half* lwqh = wqh + (size_t)lay * 3 * EMB * EMB;
        const __half* lwql = wql + (size_t)lay * 3 * EMB * EMB;
        const __half* lwph = wph + (size_t)lay * EMB * EMB;
        const __half* lwpl = wpl + (size_t)lay * EMB * EMB;
        const __half* lw1h = w1h + (size_t)lay * FFDIM * EMB;
        const __half* lw1l = w1l + (size_t)lay * FFDIM * EMB;
        const __half* lw2h = w2h + (size_t)lay * EMB * FFDIM;
        const __half* lw2l = w2l + (size_t)lay * EMB * FFDIM;

        ln_kernel<<<M, 256>>>(x, s1, c1, hbuf);
        gemm_mma256<0><<<dim3(3 * EMB / 128, M / 128), 256, SMEM_B>>>(
            hbuf, lwqh, lwql, qb, nullptr, nullptr, nullptr, M, 3 * EMB, EMB);
        flash_attn<<<dim3(NBH, 8), 256, FLASH_SMEM>>>();
        gemm_mma512<1><<<dim3(EMB / 128, M / 128), 512, SMEM_A>>>(
            abuf, lwph, lwpl, pb, x, x, nullptr, M, EMB, EMB);
        ln_kernel<<<M, 256>>>(x, s2, c2, hbuf);
        gemm_mma256<2><<<dim3(FFDIM / 128, M / 128), 256, SMEM_B>>>(
            hbuf, lw1h, lw1l, bb1, nullptr, nullptr, fbuf, M, FFDIM, EMB);
        gemm_mma512<1><<<dim3(EMB / 128, M / 128), 512, SMEM_A>>>(
            fbuf, lw2h, lw2l, bb2, x, x, nullptr, M, EMB, FFDIM);
    }

    head_kernel<<<BATCH * KLEN, 256>>>(x, w_out, b_out, out);
}